// round 14
// baseline (speedup 1.0000x reference)
#include <cuda_runtime.h>
#include <cstddef>
#include <cstdint>

// ---------------------------------------------------------------------------
// VQ-VAE forward. All GEMMs via bf16x3 emulated-fp32 mma.sync.m16n8k16.
// CTA 128x128 with 128 threads (4 warps, 2m x 2n -> 64x64 warp tile):
// minimizes smem-crossbar fragment traffic, 2 CTAs/SM. 80B-stride rows,
// ldmatrix.m8n8.x4 fragment loads, double-buffered, 1 sync/tile.
// Deconv1 parities fused via grid.z. Scratch in __device__ globals.
// ---------------------------------------------------------------------------

#define HS 256
#define NE 512

__device__ __align__(16) float g_h16[16777216];
__device__ __align__(16) float g_h8[4194304];
__device__ __align__(16) float g_t8[4194304];
__device__ __align__(16) float g_q[4194304];
__device__ __align__(16) float g_scores[8388608];
__device__ __align__(16) float g_wp[1048576];
__device__ __align__(16) float g_enorm[512];
__device__ __align__(16) float g_scale[256];
__device__ __align__(16) float g_part[512];

struct GemmP {
    const float* A; const float* W; const float* bias; const float* res; float* out;
    const float* ascale; const float* aweight;
    int N, K;
    int IC, IH, IW, OH, OW, stride, padh, padw;
    int oscale, ooffh, ooffw, oW, oHW;
    int mode;   // 0 plain, 1 bias+relu, 2 res+bias+relu
};

__device__ __forceinline__ unsigned pack_bf16x2(float lo, float hi) {
    unsigned r;
    asm("cvt.rn.bf16x2.f32 %0, %1, %2;" : "=r"(r) : "f"(hi), "f"(lo));
    return r;
}
__device__ __forceinline__ void mma_bf16(float* d, const unsigned* a, const unsigned* b) {
    asm volatile(
        "mma.sync.aligned.m16n8k16.row.col.f32.bf16.bf16.f32 "
        "{%0,%1,%2,%3}, {%4,%5,%6,%7}, {%8,%9}, {%0,%1,%2,%3};"
        : "+f"(d[0]), "+f"(d[1]), "+f"(d[2]), "+f"(d[3])
        : "r"(a[0]), "r"(a[1]), "r"(a[2]), "r"(a[3]), "r"(b[0]), "r"(b[1]));
}
__device__ __forceinline__ uint32_t smem_u32(const void* p) {
    uint32_t a;
    asm("{ .reg .u64 t; cvta.to.shared.u64 t, %1; cvt.u32.u64 %0, t; }" : "=r"(a) : "l"(p));
    return a;
}
__device__ __forceinline__ void ldsm4(unsigned* r, uint32_t addr) {
    asm volatile("ldmatrix.sync.aligned.m8n8.x4.shared.b16 {%0,%1,%2,%3}, [%4];"
                 : "=r"(r[0]), "=r"(r[1]), "=r"(r[2]), "=r"(r[3]) : "r"(addr));
}

// Row layout: 80B/row. [0,16)=high k0-7, [16,32)=high k8-15, [32,48)=low k0-7,
// [48,64)=low k8-15, [64,80) pad. A tile 128 rows @ +0; B tile @ +10240.
#define ROWB 80
#define TILEB 10240
#define BUFB 20480

// ---------------------------------------------------------------------------
// bf16x3 conv GEMM: CTA 128(M) x 128(N), 128 threads, warps 2m x 2n (64x64).
// PAR4: deconv1 parity fusion via blockIdx.z.
// ---------------------------------------------------------------------------
template<int KH, int KW, bool RMS, bool PAR4>
__global__ __launch_bounds__(128, 2) void conv_bf16(GemmP p) {
    constexpr int KHKW = KH * KW;
    __shared__ __align__(16) char smem[2 * BUFB];
    __shared__ int sY[128], sX[128], sBase[128], sObase[128];
    __shared__ float sScl[128];

    const int tid = threadIdx.x;
    const int bm = blockIdx.x * 128;
    const int bn = blockIdx.y * 128;

    int padh = p.padh, padw = p.padw, ooffh = p.ooffh, ooffw = p.ooffw;
    const float* Wbase = p.W;
    if (PAR4) {
        int z = blockIdx.z;
        int ph = z >> 1, pw = z & 1;
        padh = 1 - ph; padw = 1 - pw;
        ooffh = ph; ooffw = pw;
        Wbase += (size_t)z * 262144;
    }

    {   // 128 threads init 128 rows
        int m = bm + tid;
        int ohw = p.OH * p.OW;
        int n = m / ohw;
        int rem = m - n * ohw;
        int oh = rem / p.OW;
        int ow = rem - oh * p.OW;
        sBase[tid] = n * p.IC * p.IH * p.IW;
        sY[tid] = oh * p.stride - padh;
        sX[tid] = ow * p.stride - padw;
        sObase[tid] = n * p.N * p.oHW + (oh * p.oscale + ooffh) * p.oW
                      + (ow * p.oscale + ooffw);
        sScl[tid] = RMS ? p.ascale[n] : 1.f;
    }
    __syncthreads();

    const int IH = p.IH, IW = p.IW;
    const int r = tid;                    // this thread owns row r of A and B
    const int rby = sY[r], rbx = sX[r], rbb = sBase[r];
    const float ascl = sScl[r];
    const float* Wrow = Wbase + (size_t)(bn + r) * p.K;

    // warps 2m x 2n -> 64x64 tile
    const int w = tid >> 5, lane = tid & 31;
    const int wm = (w & 1) * 64, wn = (w >> 1) * 64;
    const int lg = lane >> 2, lk = lane & 3;

    const uint32_t sb = smem_u32(smem);
    const uint32_t aoff = (uint32_t)((lane & 15) * ROWB + (lane >> 4) * 16);
    const uint32_t boff = (uint32_t)(((lane & 7) + ((lane >> 4) << 3)) * ROWB
                                     + (lane & 8) * 2);

    float acc[4][8][4];
#pragma unroll
    for (int i = 0; i < 4; i++)
#pragma unroll
        for (int j = 0; j < 8; j++)
#pragma unroll
            for (int e = 0; e < 4; e++) acc[i][j][e] = 0.f;

    // staging: 8 packed words per operand per class (16 k -> 8 bf16x2 words)
    unsigned hA[8], lA[8], hB[8], lB[8];

    auto gather = [&](int k0) {
        float af[16], bf[16];
#pragma unroll
        for (int q = 0; q < 16; q++) {
            int k = k0 + q;
            int ic = k / KHKW;
            int kk2 = k - ic * KHKW;
            int kh = kk2 / KW;
            int kw = kk2 - kh * KW;
            int ih = rby + kh, iw = rbx + kw;
            float vv = 0.f;
            if ((unsigned)ih < (unsigned)IH && (unsigned)iw < (unsigned)IW) {
                int ii = (ic * IH + ih) * IW + iw;
                vv = p.A[rbb + ii];
                if (RMS) vv *= ascl * p.aweight[ii];
            }
            af[q] = vv;
        }
#pragma unroll
        for (int q4 = 0; q4 < 4; q4++) {
            float4 b = *(const float4*)(Wrow + k0 + q4 * 4);
            bf[q4 * 4 + 0] = b.x; bf[q4 * 4 + 1] = b.y;
            bf[q4 * 4 + 2] = b.z; bf[q4 * 4 + 3] = b.w;
        }
#pragma unroll
        for (int c = 0; c < 8; c++) {
            float v0 = af[2 * c], v1 = af[2 * c + 1];
            unsigned ph = pack_bf16x2(v0, v1);
            hA[c] = ph;
            lA[c] = pack_bf16x2(v0 - __uint_as_float(ph << 16),
                                v1 - __uint_as_float(ph & 0xFFFF0000u));
        }
#pragma unroll
        for (int c = 0; c < 8; c++) {
            float v0 = bf[2 * c], v1 = bf[2 * c + 1];
            unsigned ph = pack_bf16x2(v0, v1);
            hB[c] = ph;
            lB[c] = pack_bf16x2(v0 - __uint_as_float(ph << 16),
                                v1 - __uint_as_float(ph & 0xFFFF0000u));
        }
    };
    auto store = [&](int buf) {
        char* base = smem + buf * BUFB;
        *(uint4*)(base + r * ROWB + 0)  = *(const uint4*)&hA[0];
        *(uint4*)(base + r * ROWB + 16) = *(const uint4*)&hA[4];
        *(uint4*)(base + r * ROWB + 32) = *(const uint4*)&lA[0];
        *(uint4*)(base + r * ROWB + 48) = *(const uint4*)&lA[4];
        char* bb = base + TILEB;
        *(uint4*)(bb + r * ROWB + 0)  = *(const uint4*)&hB[0];
        *(uint4*)(bb + r * ROWB + 16) = *(const uint4*)&hB[4];
        *(uint4*)(bb + r * ROWB + 32) = *(const uint4*)&lB[0];
        *(uint4*)(bb + r * ROWB + 48) = *(const uint4*)&lB[4];
    };

    const int ntiles = p.K >> 4;
    gather(0);
    store(0);
    __syncthreads();

    for (int t = 0; t < ntiles; t++) {
        const int cur = t & 1;
        const uint32_t aBase = sb + cur * BUFB;
        const uint32_t bBase = aBase + TILEB;
        if (t + 1 < ntiles) gather((t + 1) << 4);

        unsigned bh[4][4], bl[4][4];
#pragma unroll
        for (int ntp = 0; ntp < 4; ntp++) {
            uint32_t ba = bBase + (uint32_t)((wn + ntp * 16) * ROWB) + boff;
            ldsm4(bh[ntp], ba);
            ldsm4(bl[ntp], ba + 32);
        }
#pragma unroll
        for (int mt = 0; mt < 4; mt++) {
            uint32_t aa = aBase + (uint32_t)((wm + mt * 16) * ROWB) + aoff;
            unsigned ah[4], al[4];
            ldsm4(ah, aa);
            ldsm4(al, aa + 32);
#pragma unroll
            for (int nt = 0; nt < 8; nt++) {
                const unsigned* bhp = &bh[nt >> 1][(nt & 1) * 2];
                const unsigned* blp = &bl[nt >> 1][(nt & 1) * 2];
                mma_bf16(acc[mt][nt], ah, bhp);
                mma_bf16(acc[mt][nt], al, bhp);
                mma_bf16(acc[mt][nt], ah, blp);
            }
        }
        if (t + 1 < ntiles) {
            store(cur ^ 1);
            __syncthreads();
        }
    }

    const int oHW = p.oHW;
#pragma unroll
    for (int mt = 0; mt < 4; mt++) {
#pragma unroll
        for (int hf = 0; hf < 2; hf++) {
            int ml = wm + mt * 16 + lg + hf * 8;
            int obase = sObase[ml];
#pragma unroll
            for (int nt = 0; nt < 8; nt++) {
                int oc = bn + wn + nt * 8 + lk * 2;
                float v0 = acc[mt][nt][hf * 2 + 0];
                float v1 = acc[mt][nt][hf * 2 + 1];
                if (p.bias) { v0 += p.bias[oc]; v1 += p.bias[oc + 1]; }
                if (p.mode >= 1) { v0 = fmaxf(v0, 0.f); v1 = fmaxf(v1, 0.f); }
                size_t oi0 = (size_t)obase + (size_t)oc * oHW;
                size_t oi1 = oi0 + oHW;
                if (p.mode == 2) { v0 += p.res[oi0]; v1 += p.res[oi1]; }
                p.out[oi0] = v0;
                p.out[oi1] = v1;
            }
        }
    }
}

// ---------------------------------------------------------------------------
__global__ __launch_bounds__(256) void rms_scale_kernel(const float* __restrict__ in,
                                                        float* __restrict__ scale) {
    const int n = blockIdx.x;
    const float4* xp = (const float4*)(in + (size_t)n * 16384);
    float s = 0.f;
    for (int i = threadIdx.x; i < 4096; i += 256) {
        float4 v = xp[i];
        s += v.x * v.x + v.y * v.y + v.z * v.z + v.w * v.w;
    }
    __shared__ float sh[256];
    sh[threadIdx.x] = s;
    __syncthreads();
    for (int st = 128; st > 0; st >>= 1) {
        if (threadIdx.x < st) sh[threadIdx.x] += sh[threadIdx.x + st];
        __syncthreads();
    }
    if (threadIdx.x == 0)
        scale[n] = rsqrtf(sh[0] * (1.f / 16384.f) + 1.1920929e-07f);
}

__global__ void enorm_kernel(const float* __restrict__ e, float* __restrict__ en) {
    int j = blockIdx.x * 256 + threadIdx.x;
    if (j >= NE) return;
    const float* r = e + (size_t)j * HS;
    float s = 0.f;
    for (int c = 0; c < HS; c++) { float v = r[c]; s += v * v; }
    en[j] = s;
}

__global__ __launch_bounds__(256) void vq_argmin_kernel(const float* __restrict__ scores,
                                                        const float* __restrict__ en,
                                                        const float* __restrict__ emb,
                                                        float* __restrict__ q) {
    int token = blockIdx.x * 8 + (threadIdx.x >> 5);
    int lane = threadIdx.x & 31;
    int n = token >> 6, hw = token & 63;
    const float* sc = scores + ((size_t)n * NE) * 64 + hw;
    float best = 3.4e38f;
    int bj = NE;
    for (int j = lane; j < NE; j += 32) {
        float d = en[j] - 2.f * sc[(size_t)j * 64];
        if (d < best || (d == best && j < bj)) { best = d; bj = j; }
    }
#pragma unroll
    for (int off = 16; off; off >>= 1) {
        float ob = __shfl_down_sync(0xffffffffu, best, off);
        int oj = __shfl_down_sync(0xffffffffu, bj, off);
        if (ob < best || (ob == best && oj < bj)) { best = ob; bj = oj; }
    }
    bj = __shfl_sync(0xffffffffu, bj, 0);
    const float* er = emb + (size_t)bj * HS;
    float* qp = q + (size_t)n * HS * 64 + hw;
    for (int c = lane; c < HS; c += 32) qp[(size_t)c * 64] = er[c];
}

__global__ __launch_bounds__(256) void sqdiff_kernel(const float* __restrict__ a,
                                                     const float* __restrict__ b,
                                                     float* __restrict__ part, int nvec4) {
    const float4* a4 = (const float4*)a;
    const float4* b4 = (const float4*)b;
    float s = 0.f;
    for (int i = blockIdx.x * 256 + threadIdx.x; i < nvec4; i += 256 * 256) {
        float4 va = a4[i], vb = b4[i];
        float dx = va.x - vb.x, dy = va.y - vb.y, dz = va.z - vb.z, dw = va.w - vb.w;
        s += dx * dx + dy * dy + dz * dz + dw * dw;
    }
    __shared__ float sh[256];
    sh[threadIdx.x] = s;
    __syncthreads();
    for (int st = 128; st > 0; st >>= 1) {
        if (threadIdx.x < st) sh[threadIdx.x] += sh[threadIdx.x + st];
        __syncthreads();
    }
    if (threadIdx.x == 0) part[blockIdx.x] = sh[0];
}

__global__ void finalize_kernel(const float* __restrict__ partVq,
                                const float* __restrict__ partRec,
                                float* __restrict__ out) {
    if (threadIdx.x == 0 && blockIdx.x == 0) {
        float svq = 0.f, sre = 0.f;
        for (int i = 0; i < 256; i++) { svq += partVq[i]; sre += partRec[i]; }
        float dict = svq * (1.f / 4194304.f);
        float rec = sre * (1.f / 786432.f);
        out[0] = rec + dict + dict;
        out[1] = rec;
        out[2] = dict;
        out[3] = dict;
    }
}

__global__ void prep_wp_kernel(const float* __restrict__ w, float* __restrict__ wp) {
    int idx = blockIdx.x * 256 + threadIdx.x;
    if (idx >= 1048576) return;
    int b = idx & 1;
    int a = (idx >> 1) & 1;
    int ic = (idx >> 2) & 255;
    int oc = (idx >> 10) & 255;
    int p = idx >> 18;
    int ph = p >> 1, pw = p & 1;
    int kh = ph + 2 * a, kw = pw + 2 * b;
    wp[idx] = w[((size_t)(ic * 256 + oc) * 4 + (3 - kh)) * 4 + (3 - kw)];
}

__global__ __launch_bounds__(256) void deconv2_kernel(const float* __restrict__ in,
                                                      const float* __restrict__ w,
                                                      const float* __restrict__ bias,
                                                      float* __restrict__ out) {
    __shared__ float wsh[4 * 256 * 3];
    const int n = blockIdx.x;
    const int par = blockIdx.y;
    const int ph = par >> 1, pw = par & 1;
    const int tid = threadIdx.x;

    for (int idx = tid; idx < 3072; idx += 256) {
        int oc = idx % 3;
        int rest = idx / 3;
        int ic = rest & 255;
        int t = rest >> 8;
        int a = t >> 1, b = t & 1;
        int kh = ph + 2 * a, kw = pw + 2 * b;
        wsh[idx] = w[((size_t)(ic * 3 + oc) * 4 + (3 - kh)) * 4 + (3 - kw)];
    }
    __syncthreads();

    const int i = tid >> 4, j = tid & 15;
    const int oh = 2 * i + ph, ow = 2 * j + pw;
    float acc0 = 0.f, acc1 = 0.f, acc2 = 0.f;

    int base[4];
    bool ok[4];
#pragma unroll
    for (int t = 0; t < 4; t++) {
        int a = t >> 1, b = t & 1;
        int ih = i + ph + a - 1, iw = j + pw + b - 1;
        ok[t] = ((unsigned)ih < 16u) && ((unsigned)iw < 16u);
        base[t] = ok[t] ? (n * 65536 + ih * 16 + iw) : 0;
    }
    for (int ic = 0; ic < 256; ic++) {
        int ico = ic * 256;
#pragma unroll
        for (int t = 0; t < 4; t++) {
            if (ok[t]) {
                float v = in[base[t] + ico];
                const float* wp2 = &wsh[(t * 256 + ic) * 3];
                acc0 += v * wp2[0];
                acc1 += v * wp2[1];
                acc2 += v * wp2[2];
            }
        }
    }
    size_t o = (size_t)n * 3072 + (size_t)oh * 32 + ow;
    out[o] = acc0 + bias[0];
    out[o + 1024] = acc1 + bias[1];
    out[o + 2048] = acc2 + bias[2];
}

// ---------------------------------------------------------------------------
static GemmP mkP(const float* A, const float* W, const float* bias, const float* res,
                 float* out, const float* ascale, const float* aweight,
                 int N, int K, int IC, int IH, int IW, int OH, int OW,
                 int stride, int padh, int padw,
                 int oscale, int ooffh, int ooffw, int oW, int oHW, int mode) {
    GemmP p;
    p.A = A; p.W = W; p.bias = bias; p.res = res; p.out = out;
    p.ascale = ascale; p.aweight = aweight;
    p.N = N; p.K = K; p.IC = IC; p.IH = IH; p.IW = IW; p.OH = OH; p.OW = OW;
    p.stride = stride; p.padh = padh; p.padw = padw;
    p.oscale = oscale; p.ooffh = ooffh; p.ooffw = ooffw; p.oW = oW; p.oHW = oHW;
    p.mode = mode;
    return p;
}

template<int KH, int KW, bool RMS>
static void launch_bf16(GemmP p, int M) {
    dim3 g(M / 128, p.N / 128);
    conv_bf16<KH, KW, RMS, false><<<g, 128>>>(p);
}

static void res_block(float* x, float* tmp, float* scl, const float* rmsw,
                      const float* w3, const float* b3,
                      const float* w1, const float* b1) {
    rms_scale_kernel<<<256, 256>>>(x, scl);
    {
        GemmP p = mkP(x, w3, b3, x, tmp, scl, rmsw,
                      256, 2304, 256, 8, 8, 8, 8, 1, 1, 1,
                      1, 0, 0, 8, 64, 2);
        launch_bf16<3, 3, true>(p, 16384);
    }
    rms_scale_kernel<<<256, 256>>>(tmp, scl);
    {
        GemmP p = mkP(tmp, w1, b1, tmp, x, scl, rmsw + 16384,
                      256, 256, 256, 8, 8, 8, 8, 1, 0, 0,
                      1, 0, 0, 8, 64, 2);
        launch_bf16<1, 1, true>(p, 16384);
    }
}

extern "C" void kernel_launch(void* const* d_in, const int* in_sizes, int n_in,
                              void* d_out, int out_size) {
    const float* x       = (const float*)d_in[0];
    const float* enc_w1  = (const float*)d_in[1];
    const float* enc_b1  = (const float*)d_in[2];
    const float* enc_w2  = (const float*)d_in[3];
    const float* enc_b2  = (const float*)d_in[4];
    const float* rms_w   = (const float*)d_in[5];
    const float* c3_w    = (const float*)d_in[6];
    const float* c3_b    = (const float*)d_in[7];
    const float* c1_w    = (const float*)d_in[8];
    const float* c1_b    = (const float*)d_in[9];
    const float* emb     = (const float*)d_in[10];
    const float* dec_w1  = (const float*)d_in[11];
    const float* dec_b1  = (const float*)d_in[12];
    const float* dec_w2  = (const float*)d_in[13];
    const float* dec_b2  = (const float*)d_in[14];
    float* out = (float*)d_out;

    float *h16, *h8, *t8, *q, *scores, *wp, *en, *scl, *part;
    cudaGetSymbolAddress((void**)&h16, g_h16);
    cudaGetSymbolAddress((void**)&h8, g_h8);
    cudaGetSymbolAddress((void**)&t8, g_t8);
    cudaGetSymbolAddress((void**)&q, g_q);
    cudaGetSymbolAddress((void**)&scores, g_scores);
    cudaGetSymbolAddress((void**)&wp, g_wp);
    cudaGetSymbolAddress((void**)&en, g_enorm);
    cudaGetSymbolAddress((void**)&scl, g_scale);
    cudaGetSymbolAddress((void**)&part, g_part);

    // ---- Encoder ----
    {
        GemmP p = mkP(x, enc_w1, enc_b1, nullptr, h16, nullptr, nullptr,
                      256, 48, 3, 32, 32, 16, 16, 2, 1, 1,
                      1, 0, 0, 16, 256, 1);
        launch_bf16<4, 4, false>(p, 65536);
    }
    {
        GemmP p = mkP(h16, enc_w2, enc_b2, nullptr, h8, nullptr, nullptr,
                      256, 4096, 256, 16, 16, 8, 8, 2, 1, 1,
                      1, 0, 0, 8, 64, 1);
        launch_bf16<4, 4, false>(p, 16384);
    }
    res_block(h8, t8, scl, rms_w + 0 * 32768, c3_w + 0 * 589824, c3_b + 0 * 256,
              c1_w + 0 * 65536, c1_b + 0 * 256);
    res_block(h8, t8, scl, rms_w + 1 * 32768, c3_w + 1 * 589824, c3_b + 1 * 256,
              c1_w + 1 * 65536, c1_b + 1 * 256);

    // ---- VQ (scores via bf16x3 GEMM; argmin + q gather exact) ----
    enorm_kernel<<<2, 256>>>(emb, en);
    {
        GemmP p = mkP(h8, emb, nullptr, nullptr, scores, nullptr, nullptr,
                      512, 256, 256, 8, 8, 8, 8, 1, 0, 0,
                      1, 0, 0, 8, 64, 0);
        launch_bf16<1, 1, false>(p, 16384);
    }
    vq_argmin_kernel<<<2048, 256>>>(scores, en, emb, q);
    sqdiff_kernel<<<256, 256>>>(h8, q, part, 1048576);

    // ---- Decoder ----
    res_block(q, t8, scl, rms_w + 2 * 32768, c3_w + 2 * 589824, c3_b + 2 * 256,
              c1_w + 2 * 65536, c1_b + 2 * 256);
    res_block(q, t8, scl, rms_w + 3 * 32768, c3_w + 3 * 589824, c3_b + 3 * 256,
              c1_w + 3 * 65536, c1_b + 3 * 256);

    // deconv1: 4 parity GEMMs fused into one launch via grid.z
    prep_wp_kernel<<<4096, 256>>>(dec_w1, wp);
    {
        GemmP p = mkP(q, wp, dec_b1, nullptr, h16, nullptr, nullptr,
                      256, 1024, 256, 8, 8, 8, 8, 1, 0, 0,
                      2, 0, 0, 16, 256, 1);
        conv_bf16<2, 2, false, true><<<dim3(128, 2, 4), 128>>>(p);
    }

    deconv2_kernel<<<dim3(256, 4), 256>>>(h16, dec_w2, dec_b2, out + 4);

    sqdiff_kernel<<<256, 256>>>(out + 4, x, part + 256, 196608);
    finalize_kernel<<<1, 32>>>(part, part + 256, out);
}

// round 15
// speedup vs baseline: 1.1729x; 1.1729x over previous
#include <cuda_runtime.h>
#include <cstddef>
#include <cstdint>

// ---------------------------------------------------------------------------
// VQ-VAE forward. All GEMMs via bf16x3 emulated-fp32 mma.sync.m16n8k16.
// R12 shape (best): CTA 128x128, 256 threads, warps 2m x 4n (64x32 tile),
// K-tile 16 double-buffered, 2 CTAs/SM, 80B-stride rows + ldmatrix.m8n8.x4.
// NEW: all weights pre-packed once per call to bf16 h/l words
// ([row][K/2 h | K/2 l]) so the GEMM B-path is 2 LDG.128 with no conversion.
// Deconv1 parities fused via grid.z. Scratch in __device__ globals.
// ---------------------------------------------------------------------------

#define HS 256
#define NE 512

__device__ __align__(16) float g_h16[16777216];
__device__ __align__(16) float g_h8[4194304];
__device__ __align__(16) float g_t8[4194304];
__device__ __align__(16) float g_q[4194304];
__device__ __align__(16) float g_scores[8388608];
__device__ __align__(16) unsigned g_wpack[4861952];  // packed weights (see offsets)
__device__ __align__(16) float g_enorm[512];
__device__ __align__(16) float g_scale[256];
__device__ __align__(16) float g_part[512];

// word offsets into g_wpack
#define OFF_EW1 0           // 256 rows x K48    = 12288
#define OFF_EW2 12288       // 256 x 4096        = 1048576
#define OFF_C3  1060864     // 4 x 256 x 2304    = 2359296 (589824/block)
#define OFF_C1  3420160     // 4 x 256 x 256     = 262144  (65536/block)
#define OFF_EMB 3682304     // 512 x 256         = 131072
#define OFF_WP  3813376     // 4 x 256 x 1024    = 1048576 (262144/parity)

struct GemmP {
    const float* A; const unsigned* W; const float* bias; const float* res; float* out;
    const float* ascale; const float* aweight;
    int N, K;
    int IC, IH, IW, OH, OW, stride, padh, padw;
    int oscale, ooffh, ooffw, oW, oHW;
    int mode;   // 0 plain, 1 bias+relu, 2 res+bias+relu
};

__device__ __forceinline__ unsigned pack_bf16x2(float lo, float hi) {
    unsigned r;
    asm("cvt.rn.bf16x2.f32 %0, %1, %2;" : "=r"(r) : "f"(hi), "f"(lo));
    return r;
}
__device__ __forceinline__ void mma_bf16(float* d, const unsigned* a, const unsigned* b) {
    asm volatile(
        "mma.sync.aligned.m16n8k16.row.col.f32.bf16.bf16.f32 "
        "{%0,%1,%2,%3}, {%4,%5,%6,%7}, {%8,%9}, {%0,%1,%2,%3};"
        : "+f"(d[0]), "+f"(d[1]), "+f"(d[2]), "+f"(d[3])
        : "r"(a[0]), "r"(a[1]), "r"(a[2]), "r"(a[3]), "r"(b[0]), "r"(b[1]));
}
__device__ __forceinline__ uint32_t smem_u32(const void* p) {
    uint32_t a;
    asm("{ .reg .u64 t; cvta.to.shared.u64 t, %1; cvt.u32.u64 %0, t; }" : "=r"(a) : "l"(p));
    return a;
}
__device__ __forceinline__ void ldsm4(unsigned* r, uint32_t addr) {
    asm volatile("ldmatrix.sync.aligned.m8n8.x4.shared.b16 {%0,%1,%2,%3}, [%4];"
                 : "=r"(r[0]), "=r"(r[1]), "=r"(r[2]), "=r"(r[3]) : "r"(addr));
}

// Row layout: 80B/row. [0,16)=high k0-7, [16,32)=high k8-15, [32,48)=low k0-7,
// [48,64)=low k8-15, [64,80) pad. A tile 128 rows @ +0; B tile @ +10240.
#define ROWB 80
#define TILEB 10240
#define BUFB 20480

// ---------------------------------------------------------------------------
// bf16x3 conv GEMM: CTA 128(M) x 128(N), 256 threads, warps 2m x 4n (64x32).
// PAR4: deconv1 parity fusion via blockIdx.z. B operand pre-packed h/l.
// ---------------------------------------------------------------------------
template<int KH, int KW, bool RMS, bool PAR4>
__global__ __launch_bounds__(256, 2) void conv_bf16(GemmP p) {
    constexpr int KHKW = KH * KW;
    __shared__ __align__(16) char smem[2 * BUFB];
    __shared__ int sY[128], sX[128], sBase[128], sObase[128];
    __shared__ float sScl[128];

    const int tid = threadIdx.x;
    const int bm = blockIdx.x * 128;
    const int bn = blockIdx.y * 128;

    int padh = p.padh, padw = p.padw, ooffh = p.ooffh, ooffw = p.ooffw;
    const unsigned* Wbase = p.W;
    if (PAR4) {
        int z = blockIdx.z;
        int ph = z >> 1, pw = z & 1;
        padh = 1 - ph; padw = 1 - pw;
        ooffh = ph; ooffw = pw;
        Wbase += (size_t)z * 262144;
    }

    if (tid < 128) {
        int m = bm + tid;
        int ohw = p.OH * p.OW;
        int n = m / ohw;
        int rem = m - n * ohw;
        int oh = rem / p.OW;
        int ow = rem - oh * p.OW;
        sBase[tid] = n * p.IC * p.IH * p.IW;
        sY[tid] = oh * p.stride - padh;
        sX[tid] = ow * p.stride - padw;
        sObase[tid] = n * p.N * p.oHW + (oh * p.oscale + ooffh) * p.oW
                      + (ow * p.oscale + ooffw);
        sScl[tid] = RMS ? p.ascale[n] : 1.f;
    }
    __syncthreads();

    const int IH = p.IH, IW = p.IW;
    // gather roles: row r (0..127), half selects k0-7 / k8-15
    const int r = tid & 127;
    const int half = tid >> 7;
    const int jset = half * 8;
    const int rby = sY[r], rbx = sX[r], rbb = sBase[r];
    const float ascl = sScl[r];
    const unsigned* Wrow = Wbase + (size_t)(bn + r) * p.K;   // K words per row
    const int Khalf = p.K >> 1;

    // warps 2m x 4n -> 64x32 tile
    const int w = tid >> 5, lane = tid & 31;
    const int wm = (w & 1) * 64, wn = (w >> 1) * 32;
    const int lg = lane >> 2, lk = lane & 3;

    const uint32_t sb = smem_u32(smem);
    const uint32_t aoff = (uint32_t)((lane & 15) * ROWB + (lane >> 4) * 16);
    const uint32_t boff = (uint32_t)(((lane & 7) + ((lane >> 4) << 3)) * ROWB
                                     + (lane & 8) * 2);

    float acc[4][4][4];
#pragma unroll
    for (int i = 0; i < 4; i++)
#pragma unroll
        for (int j = 0; j < 4; j++)
#pragma unroll
            for (int e = 0; e < 4; e++) acc[i][j][e] = 0.f;

    float avf[8];
    uint4 bhv, blv;

    auto gather = [&](int k0) {
#pragma unroll
        for (int q = 0; q < 8; q++) {
            int k = k0 + jset + q;
            int ic = k / KHKW;
            int kk2 = k - ic * KHKW;
            int kh = kk2 / KW;
            int kw = kk2 - kh * KW;
            int ih = rby + kh, iw = rbx + kw;
            float v = 0.f;
            if ((unsigned)ih < (unsigned)IH && (unsigned)iw < (unsigned)IW) {
                int ii = (ic * IH + ih) * IW + iw;
                v = p.A[rbb + ii];
                if (RMS) v *= ascl * p.aweight[ii];
            }
            avf[q] = v;
        }
        int k2 = (k0 + jset) >> 1;
        bhv = *(const uint4*)(Wrow + k2);
        blv = *(const uint4*)(Wrow + Khalf + k2);
    };
    auto store = [&](int buf) {
        char* base = smem + buf * BUFB;
        uint4 hv, lv;
        unsigned* hp = (unsigned*)&hv;
        unsigned* lp = (unsigned*)&lv;
#pragma unroll
        for (int c = 0; c < 4; c++) {
            float v0 = avf[2 * c], v1 = avf[2 * c + 1];
            unsigned ph = pack_bf16x2(v0, v1);
            hp[c] = ph;
            lp[c] = pack_bf16x2(v0 - __uint_as_float(ph << 16),
                                v1 - __uint_as_float(ph & 0xFFFF0000u));
        }
        *(uint4*)(base + r * ROWB + half * 16) = hv;
        *(uint4*)(base + r * ROWB + 32 + half * 16) = lv;
        char* bb = base + TILEB;
        *(uint4*)(bb + r * ROWB + half * 16) = bhv;
        *(uint4*)(bb + r * ROWB + 32 + half * 16) = blv;
    };

    const int ntiles = p.K >> 4;
    gather(0);
    store(0);
    __syncthreads();

    for (int t = 0; t < ntiles; t++) {
        const int cur = t & 1;
        const uint32_t aBase = sb + cur * BUFB;
        const uint32_t bBase = aBase + TILEB;
        if (t + 1 < ntiles) gather((t + 1) << 4);

        unsigned bh[2][4], bl[2][4];
#pragma unroll
        for (int ntp = 0; ntp < 2; ntp++) {
            uint32_t ba = bBase + (uint32_t)((wn + ntp * 16) * ROWB) + boff;
            ldsm4(bh[ntp], ba);
            ldsm4(bl[ntp], ba + 32);
        }
#pragma unroll
        for (int mt = 0; mt < 4; mt++) {
            uint32_t aa = aBase + (uint32_t)((wm + mt * 16) * ROWB) + aoff;
            unsigned ah[4], al[4];
            ldsm4(ah, aa);
            ldsm4(al, aa + 32);
#pragma unroll
            for (int nt = 0; nt < 4; nt++) {
                const unsigned* bhp = &bh[nt >> 1][(nt & 1) * 2];
                const unsigned* blp = &bl[nt >> 1][(nt & 1) * 2];
                mma_bf16(acc[mt][nt], ah, bhp);
                mma_bf16(acc[mt][nt], al, bhp);
                mma_bf16(acc[mt][nt], ah, blp);
            }
        }
        if (t + 1 < ntiles) {
            store(cur ^ 1);
            __syncthreads();
        }
    }

    const int oHW = p.oHW;
#pragma unroll
    for (int mt = 0; mt < 4; mt++) {
#pragma unroll
        for (int hf = 0; hf < 2; hf++) {
            int ml = wm + mt * 16 + lg + hf * 8;
            int obase = sObase[ml];
#pragma unroll
            for (int nt = 0; nt < 4; nt++) {
                int oc = bn + wn + nt * 8 + lk * 2;
                float v0 = acc[mt][nt][hf * 2 + 0];
                float v1 = acc[mt][nt][hf * 2 + 1];
                if (p.bias) { v0 += p.bias[oc]; v1 += p.bias[oc + 1]; }
                if (p.mode >= 1) { v0 = fmaxf(v0, 0.f); v1 = fmaxf(v1, 0.f); }
                size_t oi0 = (size_t)obase + (size_t)oc * oHW;
                size_t oi1 = oi0 + oHW;
                if (p.mode == 2) { v0 += p.res[oi0]; v1 += p.res[oi1]; }
                p.out[oi0] = v0;
                p.out[oi1] = v1;
            }
        }
    }
}

// ---------------------------------------------------------------------------
// Weight packing: fp32 row-major [rows][K] -> [row][K/2 h-words | K/2 l-words]
// ---------------------------------------------------------------------------
__global__ void pack_w_kernel(const float* __restrict__ src, unsigned* __restrict__ dst,
                              int K, int total_pairs) {
    int idx = blockIdx.x * 256 + threadIdx.x;
    if (idx >= total_pairs) return;
    int kh = K >> 1;
    int row = idx / kh;
    int k2 = idx - row * kh;
    float v0 = src[(size_t)row * K + 2 * k2];
    float v1 = src[(size_t)row * K + 2 * k2 + 1];
    unsigned ph = pack_bf16x2(v0, v1);
    unsigned pl = pack_bf16x2(v0 - __uint_as_float(ph << 16),
                              v1 - __uint_as_float(ph & 0xFFFF0000u));
    dst[(size_t)row * K + k2] = ph;
    dst[(size_t)row * K + kh + k2] = pl;
}

// deconv1 parity weights packed directly from ConvTranspose layout (in,out,4,4)
// logical row = (p, oc), K = 1024, k = ic*4 + t, t = a*2+b; kh/kw = 3-(ph+2a)/...
__global__ void prep_wp_packed_kernel(const float* __restrict__ w, unsigned* __restrict__ dst) {
    int idx = blockIdx.x * 256 + threadIdx.x;        // pair index, total 524288
    if (idx >= 524288) return;
    int k2 = idx & 511;
    int oc = (idx >> 9) & 255;
    int par = idx >> 17;
    int ph = par >> 1, pw = par & 1;
    float v[2];
#pragma unroll
    for (int e = 0; e < 2; e++) {
        int k = 2 * k2 + e;
        int ic = k >> 2;
        int t = k & 3;
        int a = t >> 1, b = t & 1;
        int kh = ph + 2 * a, kw = pw + 2 * b;
        v[e] = w[((size_t)(ic * 256 + oc) * 4 + (3 - kh)) * 4 + (3 - kw)];
    }
    unsigned hw2 = pack_bf16x2(v[0], v[1]);
    unsigned lw2 = pack_bf16x2(v[0] - __uint_as_float(hw2 << 16),
                               v[1] - __uint_as_float(hw2 & 0xFFFF0000u));
    size_t rowoff = (size_t)(par * 256 + oc) * 1024;
    dst[rowoff + k2] = hw2;
    dst[rowoff + 512 + k2] = lw2;
}

// ---------------------------------------------------------------------------
__global__ __launch_bounds__(256) void rms_scale_kernel(const float* __restrict__ in,
                                                        float* __restrict__ scale) {
    const int n = blockIdx.x;
    const float4* xp = (const float4*)(in + (size_t)n * 16384);
    float s = 0.f;
    for (int i = threadIdx.x; i < 4096; i += 256) {
        float4 v = xp[i];
        s += v.x * v.x + v.y * v.y + v.z * v.z + v.w * v.w;
    }
    __shared__ float sh[256];
    sh[threadIdx.x] = s;
    __syncthreads();
    for (int st = 128; st > 0; st >>= 1) {
        if (threadIdx.x < st) sh[threadIdx.x] += sh[threadIdx.x + st];
        __syncthreads();
    }
    if (threadIdx.x == 0)
        scale[n] = rsqrtf(sh[0] * (1.f / 16384.f) + 1.1920929e-07f);
}

__global__ void enorm_kernel(const float* __restrict__ e, float* __restrict__ en) {
    int j = blockIdx.x * 256 + threadIdx.x;
    if (j >= NE) return;
    const float* r = e + (size_t)j * HS;
    float s = 0.f;
    for (int c = 0; c < HS; c++) { float v = r[c]; s += v * v; }
    en[j] = s;
}

__global__ __launch_bounds__(256) void vq_argmin_kernel(const float* __restrict__ scores,
                                                        const float* __restrict__ en,
                                                        const float* __restrict__ emb,
                                                        float* __restrict__ q) {
    int token = blockIdx.x * 8 + (threadIdx.x >> 5);
    int lane = threadIdx.x & 31;
    int n = token >> 6, hw = token & 63;
    const float* sc = scores + ((size_t)n * NE) * 64 + hw;
    float best = 3.4e38f;
    int bj = NE;
    for (int j = lane; j < NE; j += 32) {
        float d = en[j] - 2.f * sc[(size_t)j * 64];
        if (d < best || (d == best && j < bj)) { best = d; bj = j; }
    }
#pragma unroll
    for (int off = 16; off; off >>= 1) {
        float ob = __shfl_down_sync(0xffffffffu, best, off);
        int oj = __shfl_down_sync(0xffffffffu, bj, off);
        if (ob < best || (ob == best && oj < bj)) { best = ob; bj = oj; }
    }
    bj = __shfl_sync(0xffffffffu, bj, 0);
    const float* er = emb + (size_t)bj * HS;
    float* qp = q + (size_t)n * HS * 64 + hw;
    for (int c = lane; c < HS; c += 32) qp[(size_t)c * 64] = er[c];
}

__global__ __launch_bounds__(256) void sqdiff_kernel(const float* __restrict__ a,
                                                     const float* __restrict__ b,
                                                     float* __restrict__ part, int nvec4) {
    const float4* a4 = (const float4*)a;
    const float4* b4 = (const float4*)b;
    float s = 0.f;
    for (int i = blockIdx.x * 256 + threadIdx.x; i < nvec4; i += 256 * 256) {
        float4 va = a4[i], vb = b4[i];
        float dx = va.x - vb.x, dy = va.y - vb.y, dz = va.z - vb.z, dw = va.w - vb.w;
        s += dx * dx + dy * dy + dz * dz + dw * dw;
    }
    __shared__ float sh[256];
    sh[threadIdx.x] = s;
    __syncthreads();
    for (int st = 128; st > 0; st >>= 1) {
        if (threadIdx.x < st) sh[threadIdx.x] += sh[threadIdx.x + st];
        __syncthreads();
    }
    if (threadIdx.x == 0) part[blockIdx.x] = sh[0];
}

__global__ void finalize_kernel(const float* __restrict__ partVq,
                                const float* __restrict__ partRec,
                                float* __restrict__ out) {
    if (threadIdx.x == 0 && blockIdx.x == 0) {
        float svq = 0.f, sre = 0.f;
        for (int i = 0; i < 256; i++) { svq += partVq[i]; sre += partRec[i]; }
        float dict = svq * (1.f / 4194304.f);
        float rec = sre * (1.f / 786432.f);
        out[0] = rec + dict + dict;
        out[1] = rec;
        out[2] = dict;
        out[3] = dict;
    }
}

__global__ __launch_bounds__(256) void deconv2_kernel(const float* __restrict__ in,
                                                      const float* __restrict__ w,
                                                      const float* __restrict__ bias,
                                                      float* __restrict__ out) {
    __shared__ float wsh[4 * 256 * 3];
    const int n = blockIdx.x;
    const int par = blockIdx.y;
    const int ph = par >> 1, pw = par & 1;
    const int tid = threadIdx.x;

    for (int idx = tid; idx < 3072; idx += 256) {
        int oc = idx % 3;
        int rest = idx / 3;
        int ic = rest & 255;
        int t = rest >> 8;
        int a = t >> 1, b = t & 1;
        int kh = ph + 2 * a, kw = pw + 2 * b;
        wsh[idx] = w[((size_t)(ic * 3 + oc) * 4 + (3 - kh)) * 4 + (3 - kw)];
    }
    __syncthreads();

    const int i = tid >> 4, j = tid & 15;
    const int oh = 2 * i + ph, ow = 2 * j + pw;
    float acc0 = 0.f, acc1 = 0.f, acc2 = 0.f;

    int base[4];
    bool ok[4];
#pragma unroll
    for (int t = 0; t < 4; t++) {
        int a = t >> 1, b = t & 1;
        int ih = i + ph + a - 1, iw = j + pw + b - 1;
        ok[t] = ((unsigned)ih < 16u) && ((unsigned)iw < 16u);
        base[t] = ok[t] ? (n * 65536 + ih * 16 + iw) : 0;
    }
    for (int ic = 0; ic < 256; ic++) {
        int ico = ic * 256;
#pragma unroll
        for (int t = 0; t < 4; t++) {
            if (ok[t]) {
                float v = in[base[t] + ico];
                const float* wp2 = &wsh[(t * 256 + ic) * 3];
                acc0 += v * wp2[0];
                acc1 += v * wp2[1];
                acc2 += v * wp2[2];
            }
        }
    }
    size_t o = (size_t)n * 3072 + (size_t)oh * 32 + ow;
    out[o] = acc0 + bias[0];
    out[o + 1024] = acc1 + bias[1];
    out[o + 2048] = acc2 + bias[2];
}

// ---------------------------------------------------------------------------
static GemmP mkP(const float* A, const unsigned* W, const float* bias, const float* res,
                 float* out, const float* ascale, const float* aweight,
                 int N, int K, int IC, int IH, int IW, int OH, int OW,
                 int stride, int padh, int padw,
                 int oscale, int ooffh, int ooffw, int oW, int oHW, int mode) {
    GemmP p;
    p.A = A; p.W = W; p.bias = bias; p.res = res; p.out = out;
    p.ascale = ascale; p.aweight = aweight;
    p.N = N; p.K = K; p.IC = IC; p.IH = IH; p.IW = IW; p.OH = OH; p.OW = OW;
    p.stride = stride; p.padh = padh; p.padw = padw;
    p.oscale = oscale; p.ooffh = ooffh; p.ooffw = ooffw; p.oW = oW; p.oHW = oHW;
    p.mode = mode;
    return p;
}

template<int KH, int KW, bool RMS>
static void launch_bf16(GemmP p, int M) {
    dim3 g(M / 128, p.N / 128);
    conv_bf16<KH, KW, RMS, false><<<g, 256>>>(p);
}

static void res_block(float* x, float* tmp, float* scl, const float* rmsw,
                      const unsigned* w3p, const float* b3,
                      const unsigned* w1p, const float* b1) {
    rms_scale_kernel<<<256, 256>>>(x, scl);
    {
        GemmP p = mkP(x, w3p, b3, x, tmp, scl, rmsw,
                      256, 2304, 256, 8, 8, 8, 8, 1, 1, 1,
                      1, 0, 0, 8, 64, 2);
        launch_bf16<3, 3, true>(p, 16384);
    }
    rms_scale_kernel<<<256, 256>>>(tmp, scl);
    {
        GemmP p = mkP(tmp, w1p, b1, tmp, x, scl, rmsw + 16384,
                      256, 256, 256, 8, 8, 8, 8, 1, 0, 0,
                      1, 0, 0, 8, 64, 2);
        launch_bf16<1, 1, true>(p, 16384);
    }
}

extern "C" void kernel_launch(void* const* d_in, const int* in_sizes, int n_in,
                              void* d_out, int out_size) {
    const float* x       = (const float*)d_in[0];
    const float* enc_w1  = (const float*)d_in[1];
    const float* enc_b1  = (const float*)d_in[2];
    const float* enc_w2  = (const float*)d_in[3];
    const float* enc_b2  = (const float*)d_in[4];
    const float* rms_w   = (const float*)d_in[5];
    const float* c3_w    = (const float*)d_in[6];
    const float* c3_b    = (const float*)d_in[7];
    const float* c1_w    = (const float*)d_in[8];
    const float* c1_b    = (const float*)d_in[9];
    const float* emb     = (const float*)d_in[10];
    const float* dec_w1  = (const float*)d_in[11];
    const float* dec_b1  = (const float*)d_in[12];
    const float* dec_w2  = (const float*)d_in[13];
    const float* dec_b2  = (const float*)d_in[14];
    float* out = (float*)d_out;

    float *h16, *h8, *t8, *q, *scores, *en, *scl, *part;
    unsigned* wpk;
    cudaGetSymbolAddress((void**)&h16, g_h16);
    cudaGetSymbolAddress((void**)&h8, g_h8);
    cudaGetSymbolAddress((void**)&t8, g_t8);
    cudaGetSymbolAddress((void**)&q, g_q);
    cudaGetSymbolAddress((void**)&scores, g_scores);
    cudaGetSymbolAddress((void**)&wpk, g_wpack);
    cudaGetSymbolAddress((void**)&en, g_enorm);
    cudaGetSymbolAddress((void**)&scl, g_scale);
    cudaGetSymbolAddress((void**)&part, g_part);

    // ---- Pack all weights to bf16 h/l (cheap; once per call) ----
    pack_w_kernel<<<(6144 + 255) / 256, 256>>>(enc_w1, wpk + OFF_EW1, 48, 6144);
    pack_w_kernel<<<(524288 + 255) / 256, 256>>>(enc_w2, wpk + OFF_EW2, 4096, 524288);
    pack_w_kernel<<<(1179648 + 255) / 256, 256>>>(c3_w, wpk + OFF_C3, 2304, 1179648);
    pack_w_kernel<<<(131072 + 255) / 256, 256>>>(c1_w, wpk + OFF_C1, 256, 131072);
    pack_w_kernel<<<(65536 + 255) / 256, 256>>>(emb, wpk + OFF_EMB, 256, 65536);
    prep_wp_packed_kernel<<<(524288 + 255) / 256, 256>>>(dec_w1, wpk + OFF_WP);

    // ---- Encoder ----
    {
        GemmP p = mkP(x, wpk + OFF_EW1, enc_b1, nullptr, h16, nullptr, nullptr,
                      256, 48, 3, 32, 32, 16, 16, 2, 1, 1,
                      1, 0, 0, 16, 256, 1);
        launch_bf16<4, 4, false>(p, 65536);
    }
    {
        GemmP p = mkP(h16, wpk + OFF_EW2, enc_b2, nullptr, h8, nullptr, nullptr,
                      256, 4096, 256, 16, 16, 8, 8, 2, 1, 1,
                      1, 0, 0, 8, 64, 1);
        launch_bf16<4, 4, false>(p, 16384);
    }
    res_block(h8, t8, scl, rms_w + 0 * 32768, wpk + OFF_C3 + 0 * 589824, c3_b + 0 * 256,
              wpk + OFF_C1 + 0 * 65536, c1_b + 0 * 256);
    res_block(h8, t8, scl, rms_w + 1 * 32768, wpk + OFF_C3 + 1 * 589824, c3_b + 1 * 256,
              wpk + OFF_C1 + 1 * 65536, c1_b + 1 * 256);

    // ---- VQ (scores via bf16x3 GEMM; argmin + q gather exact) ----
    enorm_kernel<<<2, 256>>>(emb, en);
    {
        GemmP p = mkP(h8, wpk + OFF_EMB, nullptr, nullptr, scores, nullptr, nullptr,
                      512, 256, 256, 8, 8, 8, 8, 1, 0, 0,
                      1, 0, 0, 8, 64, 0);
        launch_bf16<1, 1, false>(p, 16384);
    }
    vq_argmin_kernel<<<2048, 256>>>(scores, en, emb, q);
    sqdiff_kernel<<<256, 256>>>(h8, q, part, 1048576);

    // ---- Decoder ----
    res_block(q, t8, scl, rms_w + 2 * 32768, wpk + OFF_C3 + 2 * 589824, c3_b + 2 * 256,
              wpk + OFF_C1 + 2 * 65536, c1_b + 2 * 256);
    res_block(q, t8, scl, rms_w + 3 * 32768, wpk + OFF_C3 + 3 * 589824, c3_b + 3 * 256,
              wpk + OFF_C1 + 3 * 65536, c1_b + 3 * 256);

    // deconv1: 4 parity GEMMs fused into one launch via grid.z
    {
        GemmP p = mkP(q, wpk + OFF_WP, dec_b1, nullptr, h16, nullptr, nullptr,
                      256, 1024, 256, 8, 8, 8, 8, 1, 0, 0,
                      2, 0, 0, 16, 256, 1);
        conv_bf16<2, 2, false, true><<<dim3(128, 2, 4), 256>>>(p);
    }

    deconv2_kernel<<<dim3(256, 4), 256>>>(h16, dec_w2, dec_b2, out + 4);

    sqdiff_kernel<<<256, 256>>>(out + 4, x, part + 256, 196608);
    finalize_kernel<<<1, 32>>>(part, part + 256, out);
}

// round 16
// speedup vs baseline: 1.2132x; 1.0343x over previous
#include <cuda_runtime.h>
#include <cstddef>
#include <cstdint>

// ---------------------------------------------------------------------------
// VQ-VAE forward. All GEMMs via bf16x3 emulated-fp32 mma.sync.m16n8k16.
// R12 core: CTA 128x128, 256 threads, warps 2m x 4n (64x32), K-tile 16
// double-buffered, 2 CTAs/SM, 80B rows + ldmatrix.m8n8.x4.
// NEW: RMSNorm fully fused — GEMM epilogues emit per-sample sum-of-squares
// partials; the next GEMM computes the scale inline at init (no rms kernels).
// q's RMS uses tok_en (codebook norms) from vq_argmin. deconv2 fuses the
// reconstruction-loss partials. Deconv1 parities fused via grid.z.
// ---------------------------------------------------------------------------

#define HS 256
#define NE 512
#define EPS 1.1920929e-07f

__device__ __align__(16) float g_h16[16777216];
__device__ __align__(16) float g_h8[4194304];
__device__ __align__(16) float g_t8[4194304];
__device__ __align__(16) float g_q[4194304];
__device__ __align__(16) float g_scores[8388608];
__device__ __align__(16) float g_wp[1048576];
__device__ __align__(16) float g_enorm[512];
__device__ __align__(16) float g_tok_en[16384];
__device__ __align__(16) float g_pA[512];       // per-sample sq partials [n][2]
__device__ __align__(16) float g_pB[512];
__device__ __align__(16) float g_part[2048];    // [0:256) vq; [256:1280) rec

struct GemmP {
    const float* A; const float* W; const float* bias; const float* res; float* out;
    const float* sqin;    // per-sample sq partials [n][2] (RMS source) or null
    const float* tokin;   // per-token en (RMS source for q) or null
    const float* aweight; // rms elementwise weight (16384) or null
    float* sqout;         // per-sample sq partials out [n][2] or null
    int N, K;
    int IC, IH, IW, OH, OW, stride, padh, padw;
    int oscale, ooffh, ooffw, oW, oHW;
    int mode;   // 0 plain, 1 bias+relu, 2 res+bias+relu
};

__device__ __forceinline__ unsigned pack_bf16x2(float lo, float hi) {
    unsigned r;
    asm("cvt.rn.bf16x2.f32 %0, %1, %2;" : "=r"(r) : "f"(hi), "f"(lo));
    return r;
}
__device__ __forceinline__ void mma_bf16(float* d, const unsigned* a, const unsigned* b) {
    asm volatile(
        "mma.sync.aligned.m16n8k16.row.col.f32.bf16.bf16.f32 "
        "{%0,%1,%2,%3}, {%4,%5,%6,%7}, {%8,%9}, {%0,%1,%2,%3};"
        : "+f"(d[0]), "+f"(d[1]), "+f"(d[2]), "+f"(d[3])
        : "r"(a[0]), "r"(a[1]), "r"(a[2]), "r"(a[3]), "r"(b[0]), "r"(b[1]));
}
__device__ __forceinline__ uint32_t smem_u32(const void* p) {
    uint32_t a;
    asm("{ .reg .u64 t; cvta.to.shared.u64 t, %1; cvt.u32.u64 %0, t; }" : "=r"(a) : "l"(p));
    return a;
}
__device__ __forceinline__ void ldsm4(unsigned* r, uint32_t addr) {
    asm volatile("ldmatrix.sync.aligned.m8n8.x4.shared.b16 {%0,%1,%2,%3}, [%4];"
                 : "=r"(r[0]), "=r"(r[1]), "=r"(r[2]), "=r"(r[3]) : "r"(addr));
}

#define ROWB 80
#define TILEB 10240
#define BUFB 20480

// ---------------------------------------------------------------------------
// bf16x3 conv GEMM. RMS: scale A rows. PAR4: deconv1 fusion. SQ: emit partials.
// ---------------------------------------------------------------------------
template<int KH, int KW, bool RMS, bool PAR4, bool SQ>
__global__ __launch_bounds__(256, 2) void conv_bf16(GemmP p) {
    constexpr int KHKW = KH * KW;
    __shared__ __align__(16) char smem[2 * BUFB];
    __shared__ int sY[128], sX[128], sBase[128], sObase[128];
    __shared__ float sScl[128];
    __shared__ float rsum[2][256];

    const int tid = threadIdx.x;
    const int bm = blockIdx.x * 128;
    const int bn = blockIdx.y * 128;

    int padh = p.padh, padw = p.padw, ooffh = p.ooffh, ooffw = p.ooffw;
    const float* Wbase = p.W;
    if (PAR4) {
        int z = blockIdx.z;
        int ph = z >> 1, pw = z & 1;
        padh = 1 - ph; padw = 1 - pw;
        ooffh = ph; ooffw = pw;
        Wbase += (size_t)z * 262144;
    }

    if (tid < 128) {
        int m = bm + tid;
        int ohw = p.OH * p.OW;
        int n = m / ohw;
        int rem = m - n * ohw;
        int oh = rem / p.OW;
        int ow = rem - oh * p.OW;
        sBase[tid] = n * p.IC * p.IH * p.IW;
        sY[tid] = oh * p.stride - padh;
        sX[tid] = ow * p.stride - padw;
        sObase[tid] = n * p.N * p.oHW + (oh * p.oscale + ooffh) * p.oW
                      + (ow * p.oscale + ooffw);
        float scl = 1.f;
        if (RMS) {
            float s;
            if (p.sqin) {
                s = p.sqin[n * 2] + p.sqin[n * 2 + 1];
            } else {
                s = 0.f;
                const float* te = p.tokin + n * 64;
                for (int i = 0; i < 64; i++) s += te[i];
            }
            scl = rsqrtf(s * (1.f / 16384.f) + EPS);
        }
        sScl[tid] = scl;
    }
    __syncthreads();

    const int IH = p.IH, IW = p.IW;
    const int r = tid & 127;
    const int half = tid >> 7;
    const int jset = half * 8;
    const int rby = sY[r], rbx = sX[r], rbb = sBase[r];
    const float ascl = sScl[r];
    const float* Wrow = Wbase + (size_t)(bn + r) * p.K;

    const int w = tid >> 5, lane = tid & 31;
    const int wm = (w & 1) * 64, wn = (w >> 1) * 32;
    const int lg = lane >> 2, lk = lane & 3;

    const uint32_t sb = smem_u32(smem);
    const uint32_t aoff = (uint32_t)((lane & 15) * ROWB + (lane >> 4) * 16);
    const uint32_t boff = (uint32_t)(((lane & 7) + ((lane >> 4) << 3)) * ROWB
                                     + (lane & 8) * 2);

    float acc[4][4][4];
#pragma unroll
    for (int i = 0; i < 4; i++)
#pragma unroll
        for (int j = 0; j < 4; j++)
#pragma unroll
            for (int e = 0; e < 4; e++) acc[i][j][e] = 0.f;

    float avf[8], bvf[8];

    auto gather = [&](int k0) {
#pragma unroll
        for (int q = 0; q < 8; q++) {
            int k = k0 + jset + q;
            int ic = k / KHKW;
            int kk2 = k - ic * KHKW;
            int kh = kk2 / KW;
            int kw = kk2 - kh * KW;
            int ih = rby + kh, iw = rbx + kw;
            float v = 0.f;
            if ((unsigned)ih < (unsigned)IH && (unsigned)iw < (unsigned)IW) {
                int ii = (ic * IH + ih) * IW + iw;
                v = p.A[rbb + ii];
                if (RMS) v *= ascl * p.aweight[ii];
            }
            avf[q] = v;
        }
#pragma unroll
        for (int q4 = 0; q4 < 2; q4++) {
            float4 b = *(const float4*)(Wrow + k0 + jset + q4 * 4);
            bvf[q4 * 4 + 0] = b.x; bvf[q4 * 4 + 1] = b.y;
            bvf[q4 * 4 + 2] = b.z; bvf[q4 * 4 + 3] = b.w;
        }
    };
    auto store = [&](int buf) {
        char* base = smem + buf * BUFB;
        uint4 hv, lv;
        unsigned* hp = (unsigned*)&hv;
        unsigned* lp = (unsigned*)&lv;
#pragma unroll
        for (int c = 0; c < 4; c++) {
            float v0 = avf[2 * c], v1 = avf[2 * c + 1];
            unsigned ph = pack_bf16x2(v0, v1);
            hp[c] = ph;
            lp[c] = pack_bf16x2(v0 - __uint_as_float(ph << 16),
                                v1 - __uint_as_float(ph & 0xFFFF0000u));
        }
        *(uint4*)(base + r * ROWB + half * 16) = hv;
        *(uint4*)(base + r * ROWB + 32 + half * 16) = lv;
#pragma unroll
        for (int c = 0; c < 4; c++) {
            float v0 = bvf[2 * c], v1 = bvf[2 * c + 1];
            unsigned ph = pack_bf16x2(v0, v1);
            hp[c] = ph;
            lp[c] = pack_bf16x2(v0 - __uint_as_float(ph << 16),
                                v1 - __uint_as_float(ph & 0xFFFF0000u));
        }
        char* bb = base + TILEB;
        *(uint4*)(bb + r * ROWB + half * 16) = hv;
        *(uint4*)(bb + r * ROWB + 32 + half * 16) = lv;
    };

    const int ntiles = p.K >> 4;
    gather(0);
    store(0);
    __syncthreads();

    for (int t = 0; t < ntiles; t++) {
        const int cur = t & 1;
        const uint32_t aBase = sb + cur * BUFB;
        const uint32_t bBase = aBase + TILEB;
        if (t + 1 < ntiles) gather((t + 1) << 4);

        unsigned bh[2][4], bl[2][4];
#pragma unroll
        for (int ntp = 0; ntp < 2; ntp++) {
            uint32_t ba = bBase + (uint32_t)((wn + ntp * 16) * ROWB) + boff;
            ldsm4(bh[ntp], ba);
            ldsm4(bl[ntp], ba + 32);
        }
#pragma unroll
        for (int mt = 0; mt < 4; mt++) {
            uint32_t aa = aBase + (uint32_t)((wm + mt * 16) * ROWB) + aoff;
            unsigned ah[4], al[4];
            ldsm4(ah, aa);
            ldsm4(al, aa + 32);
#pragma unroll
            for (int nt = 0; nt < 4; nt++) {
                const unsigned* bhp = &bh[nt >> 1][(nt & 1) * 2];
                const unsigned* blp = &bl[nt >> 1][(nt & 1) * 2];
                mma_bf16(acc[mt][nt], ah, bhp);
                mma_bf16(acc[mt][nt], al, bhp);
                mma_bf16(acc[mt][nt], ah, blp);
            }
        }
        if (t + 1 < ntiles) {
            store(cur ^ 1);
            __syncthreads();
        }
    }

    const int oHW = p.oHW;
    float sq0 = 0.f, sq1 = 0.f;
#pragma unroll
    for (int mt = 0; mt < 4; mt++) {
#pragma unroll
        for (int hf = 0; hf < 2; hf++) {
            int ml = wm + mt * 16 + lg + hf * 8;
            int obase = sObase[ml];
#pragma unroll
            for (int nt = 0; nt < 4; nt++) {
                int oc = bn + wn + nt * 8 + lk * 2;
                float v0 = acc[mt][nt][hf * 2 + 0];
                float v1 = acc[mt][nt][hf * 2 + 1];
                if (p.bias) { v0 += p.bias[oc]; v1 += p.bias[oc + 1]; }
                if (p.mode >= 1) { v0 = fmaxf(v0, 0.f); v1 = fmaxf(v1, 0.f); }
                size_t oi0 = (size_t)obase + (size_t)oc * oHW;
                size_t oi1 = oi0 + oHW;
                if (p.mode == 2) { v0 += p.res[oi0]; v1 += p.res[oi1]; }
                p.out[oi0] = v0;
                p.out[oi1] = v1;
                if (SQ) {
                    float s = v0 * v0 + v1 * v1;
                    if (ml < 64) sq0 += s; else sq1 += s;
                }
            }
        }
    }
    if (SQ) {
        rsum[0][tid] = sq0;
        rsum[1][tid] = sq1;
        __syncthreads();
        for (int st = 128; st > 0; st >>= 1) {
            if (tid < st) {
                rsum[0][tid] += rsum[0][tid + st];
                rsum[1][tid] += rsum[1][tid + st];
            }
            __syncthreads();
        }
        if (tid == 0) {
            p.sqout[(blockIdx.x * 2 + 0) * 2 + blockIdx.y] = rsum[0][0];
            p.sqout[(blockIdx.x * 2 + 1) * 2 + blockIdx.y] = rsum[1][0];
        }
    }
}

// ---------------------------------------------------------------------------
__global__ void enorm_kernel(const float* __restrict__ e, float* __restrict__ en) {
    int j = blockIdx.x * 256 + threadIdx.x;
    if (j >= NE) return;
    const float* r = e + (size_t)j * HS;
    float s = 0.f;
    for (int c = 0; c < HS; c++) { float v = r[c]; s += v * v; }
    en[j] = s;
}

// VQ argmin + q gather + tok_en (per-token sum of q^2 = en[bj])
__global__ __launch_bounds__(256) void vq_argmin_kernel(const float* __restrict__ scores,
                                                        const float* __restrict__ en,
                                                        const float* __restrict__ emb,
                                                        float* __restrict__ q,
                                                        float* __restrict__ tok_en) {
    int token = blockIdx.x * 8 + (threadIdx.x >> 5);
    int lane = threadIdx.x & 31;
    int n = token >> 6, hw = token & 63;
    const float* sc = scores + ((size_t)n * NE) * 64 + hw;
    float best = 3.4e38f;
    int bj = NE;
    for (int j = lane; j < NE; j += 32) {
        float d = en[j] - 2.f * sc[(size_t)j * 64];
        if (d < best || (d == best && j < bj)) { best = d; bj = j; }
    }
#pragma unroll
    for (int off = 16; off; off >>= 1) {
        float ob = __shfl_down_sync(0xffffffffu, best, off);
        int oj = __shfl_down_sync(0xffffffffu, bj, off);
        if (ob < best || (ob == best && oj < bj)) { best = ob; bj = oj; }
    }
    bj = __shfl_sync(0xffffffffu, bj, 0);
    const float* er = emb + (size_t)bj * HS;
    float* qp = q + (size_t)n * HS * 64 + hw;
    for (int c = lane; c < HS; c += 32) qp[(size_t)c * 64] = er[c];
    if (lane == 0) tok_en[token] = en[bj];
}

__global__ __launch_bounds__(256) void sqdiff_kernel(const float* __restrict__ a,
                                                     const float* __restrict__ b,
                                                     float* __restrict__ part, int nvec4) {
    const float4* a4 = (const float4*)a;
    const float4* b4 = (const float4*)b;
    float s = 0.f;
    for (int i = blockIdx.x * 256 + threadIdx.x; i < nvec4; i += 256 * 256) {
        float4 va = a4[i], vb = b4[i];
        float dx = va.x - vb.x, dy = va.y - vb.y, dz = va.z - vb.z, dw = va.w - vb.w;
        s += dx * dx + dy * dy + dz * dz + dw * dw;
    }
    __shared__ float sh[256];
    sh[threadIdx.x] = s;
    __syncthreads();
    for (int st = 128; st > 0; st >>= 1) {
        if (threadIdx.x < st) sh[threadIdx.x] += sh[threadIdx.x + st];
        __syncthreads();
    }
    if (threadIdx.x == 0) part[blockIdx.x] = sh[0];
}

__global__ void finalize_kernel(const float* __restrict__ partVq,
                                const float* __restrict__ partRec,
                                float* __restrict__ out) {
    if (threadIdx.x == 0 && blockIdx.x == 0) {
        float svq = 0.f, sre = 0.f;
        for (int i = 0; i < 256; i++) svq += partVq[i];
        for (int i = 0; i < 1024; i++) sre += partRec[i];
        float dict = svq * (1.f / 4194304.f);
        float rec = sre * (1.f / 786432.f);
        out[0] = rec + dict + dict;
        out[1] = rec;
        out[2] = dict;
        out[3] = dict;
    }
}

__global__ void prep_wp_kernel(const float* __restrict__ w, float* __restrict__ wp) {
    int idx = blockIdx.x * 256 + threadIdx.x;
    if (idx >= 1048576) return;
    int b = idx & 1;
    int a = (idx >> 1) & 1;
    int ic = (idx >> 2) & 255;
    int oc = (idx >> 10) & 255;
    int p = idx >> 18;
    int ph = p >> 1, pw = p & 1;
    int kh = ph + 2 * a, kw = pw + 2 * b;
    wp[idx] = w[((size_t)(ic * 256 + oc) * 4 + (3 - kh)) * 4 + (3 - kw)];
}

// deconv2 + fused reconstruction-loss partials
__global__ __launch_bounds__(256) void deconv2_kernel(const float* __restrict__ in,
                                                      const float* __restrict__ w,
                                                      const float* __restrict__ bias,
                                                      const float* __restrict__ x,
                                                      float* __restrict__ out,
                                                      float* __restrict__ partRec) {
    __shared__ float wsh[4 * 256 * 3];
    const int n = blockIdx.x;
    const int par = blockIdx.y;
    const int ph = par >> 1, pw = par & 1;
    const int tid = threadIdx.x;

    for (int idx = tid; idx < 3072; idx += 256) {
        int oc = idx % 3;
        int rest = idx / 3;
        int ic = rest & 255;
        int t = rest >> 8;
        int a = t >> 1, b = t & 1;
        int kh = ph + 2 * a, kw = pw + 2 * b;
        wsh[idx] = w[((size_t)(ic * 3 + oc) * 4 + (3 - kh)) * 4 + (3 - kw)];
    }
    __syncthreads();

    const int i = tid >> 4, j = tid & 15;
    const int oh = 2 * i + ph, ow = 2 * j + pw;
    float acc0 = 0.f, acc1 = 0.f, acc2 = 0.f;

    int base[4];
    bool ok[4];
#pragma unroll
    for (int t = 0; t < 4; t++) {
        int a = t >> 1, b = t & 1;
        int ih = i + ph + a - 1, iw = j + pw + b - 1;
        ok[t] = ((unsigned)ih < 16u) && ((unsigned)iw < 16u);
        base[t] = ok[t] ? (n * 65536 + ih * 16 + iw) : 0;
    }
    for (int ic = 0; ic < 256; ic++) {
        int ico = ic * 256;
#pragma unroll
        for (int t = 0; t < 4; t++) {
            if (ok[t]) {
                float v = in[base[t] + ico];
                const float* wp2 = &wsh[(t * 256 + ic) * 3];
                acc0 += v * wp2[0];
                acc1 += v * wp2[1];
                acc2 += v * wp2[2];
            }
        }
    }
    size_t o = (size_t)n * 3072 + (size_t)oh * 32 + ow;
    float v0 = acc0 + bias[0];
    float v1 = acc1 + bias[1];
    float v2 = acc2 + bias[2];
    out[o] = v0;
    out[o + 1024] = v1;
    out[o + 2048] = v2;
    float d0 = v0 - x[o], d1 = v1 - x[o + 1024], d2 = v2 - x[o + 2048];
    float ds = d0 * d0 + d1 * d1 + d2 * d2;
    __shared__ float rs[256];
    rs[tid] = ds;
    __syncthreads();
    for (int st = 128; st > 0; st >>= 1) {
        if (tid < st) rs[tid] += rs[tid + st];
        __syncthreads();
    }
    if (tid == 0) partRec[n * 4 + par] = rs[0];
}

// ---------------------------------------------------------------------------
static GemmP mkP(const float* A, const float* W, const float* bias, const float* res,
                 float* out, const float* sqin, const float* tokin, const float* aweight,
                 float* sqout,
                 int N, int K, int IC, int IH, int IW, int OH, int OW,
                 int stride, int padh, int padw,
                 int oscale, int ooffh, int ooffw, int oW, int oHW, int mode) {
    GemmP p;
    p.A = A; p.W = W; p.bias = bias; p.res = res; p.out = out;
    p.sqin = sqin; p.tokin = tokin; p.aweight = aweight; p.sqout = sqout;
    p.N = N; p.K = K; p.IC = IC; p.IH = IH; p.IW = IW; p.OH = OH; p.OW = OW;
    p.stride = stride; p.padh = padh; p.padw = padw;
    p.oscale = oscale; p.ooffh = ooffh; p.ooffw = ooffw; p.oW = oW; p.oHW = oHW;
    p.mode = mode;
    return p;
}

// res block: x -> x, rms scales from fused partials. sqinX: partials of x.
// c3 writes partials of tmp into pT; c1 reads pT, writes partials of new x
// into pX2 (or null at chain end).
static void res_block(float* x, float* tmp,
                      const float* sqinX, const float* tokinX,
                      float* pT, float* pX2,
                      const float* rmsw,
                      const float* w3, const float* b3,
                      const float* w1, const float* b1) {
    {
        GemmP p = mkP(x, w3, b3, x, tmp, sqinX, tokinX, rmsw, pT,
                      256, 2304, 256, 8, 8, 8, 8, 1, 1, 1,
                      1, 0, 0, 8, 64, 2);
        conv_bf16<3, 3, true, false, true><<<dim3(128, 2), 256>>>(p);
    }
    if (pX2) {
        GemmP p = mkP(tmp, w1, b1, tmp, x, pT, nullptr, rmsw + 16384, pX2,
                      256, 256, 256, 8, 8, 8, 8, 1, 0, 0,
                      1, 0, 0, 8, 64, 2);
        conv_bf16<1, 1, true, false, true><<<dim3(128, 2), 256>>>(p);
    } else {
        GemmP p = mkP(tmp, w1, b1, tmp, x, pT, nullptr, rmsw + 16384, nullptr,
                      256, 256, 256, 8, 8, 8, 8, 1, 0, 0,
                      1, 0, 0, 8, 64, 2);
        conv_bf16<1, 1, true, false, false><<<dim3(128, 2), 256>>>(p);
    }
}

extern "C" void kernel_launch(void* const* d_in, const int* in_sizes, int n_in,
                              void* d_out, int out_size) {
    const float* x       = (const float*)d_in[0];
    const float* enc_w1  = (const float*)d_in[1];
    const float* enc_b1  = (const float*)d_in[2];
    const float* enc_w2  = (const float*)d_in[3];
    const float* enc_b2  = (const float*)d_in[4];
    const float* rms_w   = (const float*)d_in[5];
    const float* c3_w    = (const float*)d_in[6];
    const float* c3_b    = (const float*)d_in[7];
    const float* c1_w    = (const float*)d_in[8];
    const float* c1_b    = (const float*)d_in[9];
    const float* emb     = (const float*)d_in[10];
    const float* dec_w1  = (const float*)d_in[11];
    const float* dec_b1  = (const float*)d_in[12];
    const float* dec_w2  = (const float*)d_in[13];
    const float* dec_b2  = (const float*)d_in[14];
    float* out = (float*)d_out;

    float *h16, *h8, *t8, *q, *scores, *wp, *en, *tok, *pA, *pB, *part;
    cudaGetSymbolAddress((void**)&h16, g_h16);
    cudaGetSymbolAddress((void**)&h8, g_h8);
    cudaGetSymbolAddress((void**)&t8, g_t8);
    cudaGetSymbolAddress((void**)&q, g_q);
    cudaGetSymbolAddress((void**)&scores, g_scores);
    cudaGetSymbolAddress((void**)&wp, g_wp);
    cudaGetSymbolAddress((void**)&en, g_enorm);
    cudaGetSymbolAddress((void**)&tok, g_tok_en);
    cudaGetSymbolAddress((void**)&pA, g_pA);
    cudaGetSymbolAddress((void**)&pB, g_pB);
    cudaGetSymbolAddress((void**)&part, g_part);

    // ---- Encoder ----
    {   // conv1: no rms, no partials
        GemmP p = mkP(x, enc_w1, enc_b1, nullptr, h16, nullptr, nullptr, nullptr, nullptr,
                      256, 48, 3, 32, 32, 16, 16, 2, 1, 1,
                      1, 0, 0, 16, 256, 1);
        conv_bf16<4, 4, false, false, false><<<dim3(512, 2), 256>>>(p);
    }
    {   // conv2: emits partials of h8 -> pA
        GemmP p = mkP(h16, enc_w2, enc_b2, nullptr, h8, nullptr, nullptr, nullptr, pA,
                      256, 4096, 256, 16, 16, 8, 8, 2, 1, 1,
                      1, 0, 0, 8, 64, 1);
        conv_bf16<4, 4, false, false, true><<<dim3(128, 2), 256>>>(p);
    }
    // enc res1: rms(h8) from pA; c3 -> pB(tmp); c1 -> pA(h8 new)
    res_block(h8, t8, pA, nullptr, pB, pA, rms_w + 0 * 32768,
              c3_w + 0 * 589824, c3_b + 0 * 256, c1_w + 0 * 65536, c1_b + 0 * 256);
    // enc res2: rms(h8) from pA; c3 -> pB; c1 -> no partials (h8 final)
    res_block(h8, t8, pA, nullptr, pB, nullptr, rms_w + 1 * 32768,
              c3_w + 1 * 589824, c3_b + 1 * 256, c1_w + 1 * 65536, c1_b + 1 * 256);

    // ---- VQ ----
    enorm_kernel<<<2, 256>>>(emb, en);
    {   // scores (plain)
        GemmP p = mkP(h8, emb, nullptr, nullptr, scores, nullptr, nullptr, nullptr, nullptr,
                      512, 256, 256, 8, 8, 8, 8, 1, 0, 0,
                      1, 0, 0, 8, 64, 0);
        conv_bf16<1, 1, false, false, false><<<dim3(128, 4), 256>>>(p);
    }
    vq_argmin_kernel<<<2048, 256>>>(scores, en, emb, q, tok);
    sqdiff_kernel<<<256, 256>>>(h8, q, part, 1048576);

    // ---- Decoder ----
    // dec res1: rms(q) via tok_en; c3 -> pB; c1 -> pA
    res_block(q, t8, nullptr, tok, pB, pA, rms_w + 2 * 32768,
              c3_w + 2 * 589824, c3_b + 2 * 256, c1_w + 2 * 65536, c1_b + 2 * 256);
    // dec res2: rms(q) from pA; c3 -> pB; c1 -> none (q final)
    res_block(q, t8, pA, nullptr, pB, nullptr, rms_w + 3 * 32768,
              c3_w + 3 * 589824, c3_b + 3 * 256, c1_w + 3 * 65536, c1_b + 3 * 256);

    // deconv1: fused parities
    prep_wp_kernel<<<4096, 256>>>(dec_w1, wp);
    {
        GemmP p = mkP(q, wp, dec_b1, nullptr, h16, nullptr, nullptr, nullptr, nullptr,
                      256, 1024, 256, 8, 8, 8, 8, 1, 0, 0,
                      2, 0, 0, 16, 256, 1);
        conv_bf16<2, 2, false, true, false><<<dim3(128, 2, 4), 256>>>(p);
    }

    // deconv2 + fused rec-loss partials
    deconv2_kernel<<<dim3(256, 4), 256>>>(h16, dec_w2, dec_b2, x, out + 4, part + 256);

    finalize_kernel<<<1, 32>>>(part, part + 256, out);
}

// round 17
// speedup vs baseline: 1.2590x; 1.0378x over previous
#include <cuda_runtime.h>
#include <cuda_fp16.h>
#include <cstddef>
#include <cstdint>

// ---------------------------------------------------------------------------
// VQ-VAE forward. GEMMs via emulated-fp32 mma.sync.m16n8k16:
//   encoder + VQ scores: bf16x3 (err ~2^-18, protects argmin)
//   decoder (post-argmin): fp16x2 (err ~2^-12, 2 MMAs/k16, no B-low part)
// R12 core: CTA 128x128, 256 thr, warps 2m x 4n (64x32), K-tile 16 double-
// buffered, 2 CTAs/SM, 80B rows + ldmatrix.m8n8.x4. RMS fused into GEMMs
// (per-sample sq partials / tok_en). deconv2 fuses rec-loss partials.
// Deconv1 parities fused via grid.z. Scratch in __device__ globals.
// ---------------------------------------------------------------------------

#define HS 256
#define NE 512
#define EPS 1.1920929e-07f

__device__ __align__(16) float g_h16[16777216];
__device__ __align__(16) float g_h8[4194304];
__device__ __align__(16) float g_t8[4194304];
__device__ __align__(16) float g_q[4194304];
__device__ __align__(16) float g_scores[8388608];
__device__ __align__(16) float g_wp[1048576];
__device__ __align__(16) float g_enorm[512];
__device__ __align__(16) float g_tok_en[16384];
__device__ __align__(16) float g_pA[512];
__device__ __align__(16) float g_pB[512];
__device__ __align__(16) float g_part[2048];

struct GemmP {
    const float* A; const float* W; const float* bias; const float* res; float* out;
    const float* sqin; const float* tokin; const float* aweight;
    float* sqout;
    int N, K;
    int IC, IH, IW, OH, OW, stride, padh, padw;
    int oscale, ooffh, ooffw, oW, oHW;
    int mode;   // 0 plain, 1 bias+relu, 2 res+bias+relu
};

__device__ __forceinline__ unsigned pack_bf16x2(float lo, float hi) {
    unsigned r;
    asm("cvt.rn.bf16x2.f32 %0, %1, %2;" : "=r"(r) : "f"(hi), "f"(lo));
    return r;
}
__device__ __forceinline__ unsigned pack_f16x2(float lo, float hi) {
    unsigned r;
    asm("cvt.rn.f16x2.f32 %0, %1, %2;" : "=r"(r) : "f"(hi), "f"(lo));
    return r;
}
__device__ __forceinline__ void mma_bf16(float* d, const unsigned* a, const unsigned* b) {
    asm volatile(
        "mma.sync.aligned.m16n8k16.row.col.f32.bf16.bf16.f32 "
        "{%0,%1,%2,%3}, {%4,%5,%6,%7}, {%8,%9}, {%0,%1,%2,%3};"
        : "+f"(d[0]), "+f"(d[1]), "+f"(d[2]), "+f"(d[3])
        : "r"(a[0]), "r"(a[1]), "r"(a[2]), "r"(a[3]), "r"(b[0]), "r"(b[1]));
}
__device__ __forceinline__ void mma_f16(float* d, const unsigned* a, const unsigned* b) {
    asm volatile(
        "mma.sync.aligned.m16n8k16.row.col.f32.f16.f16.f32 "
        "{%0,%1,%2,%3}, {%4,%5,%6,%7}, {%8,%9}, {%0,%1,%2,%3};"
        : "+f"(d[0]), "+f"(d[1]), "+f"(d[2]), "+f"(d[3])
        : "r"(a[0]), "r"(a[1]), "r"(a[2]), "r"(a[3]), "r"(b[0]), "r"(b[1]));
}
__device__ __forceinline__ uint32_t smem_u32(const void* p) {
    uint32_t a;
    asm("{ .reg .u64 t; cvta.to.shared.u64 t, %1; cvt.u32.u64 %0, t; }" : "=r"(a) : "l"(p));
    return a;
}
__device__ __forceinline__ void ldsm4(unsigned* r, uint32_t addr) {
    asm volatile("ldmatrix.sync.aligned.m8n8.x4.shared.b16 {%0,%1,%2,%3}, [%4];"
                 : "=r"(r[0]), "=r"(r[1]), "=r"(r[2]), "=r"(r[3]) : "r"(addr));
}

#define ROWB 80
#define TILEB 10240
#define BUFB 20480

// PREC: 0 = bf16x3 (3 MMA, B h+l), 1 = fp16x2 (2 MMA, B high only)
template<int KH, int KW, bool RMS, bool PAR4, bool SQ, int PREC>
__global__ __launch_bounds__(256, 2) void conv_mma(GemmP p) {
    constexpr int KHKW = KH * KW;
    __shared__ __align__(16) char smem[2 * BUFB];
    __shared__ int sY[128], sX[128], sBase[128], sObase[128];
    __shared__ float sScl[128];
    __shared__ float rsum[2][256];

    const int tid = threadIdx.x;
    const int bm = blockIdx.x * 128;
    const int bn = blockIdx.y * 128;

    int padh = p.padh, padw = p.padw, ooffh = p.ooffh, ooffw = p.ooffw;
    const float* Wbase = p.W;
    if (PAR4) {
        int z = blockIdx.z;
        int ph = z >> 1, pw = z & 1;
        padh = 1 - ph; padw = 1 - pw;
        ooffh = ph; ooffw = pw;
        Wbase += (size_t)z * 262144;
    }

    if (tid < 128) {
        int m = bm + tid;
        int ohw = p.OH * p.OW;
        int n = m / ohw;
        int rem = m - n * ohw;
        int oh = rem / p.OW;
        int ow = rem - oh * p.OW;
        sBase[tid] = n * p.IC * p.IH * p.IW;
        sY[tid] = oh * p.stride - padh;
        sX[tid] = ow * p.stride - padw;
        sObase[tid] = n * p.N * p.oHW + (oh * p.oscale + ooffh) * p.oW
                      + (ow * p.oscale + ooffw);
        float scl = 1.f;
        if (RMS) {
            float s;
            if (p.sqin) {
                s = p.sqin[n * 2] + p.sqin[n * 2 + 1];
            } else {
                s = 0.f;
                const float* te = p.tokin + n * 64;
                for (int i = 0; i < 64; i++) s += te[i];
            }
            scl = rsqrtf(s * (1.f / 16384.f) + EPS);
        }
        sScl[tid] = scl;
    }
    __syncthreads();

    const int IH = p.IH, IW = p.IW;
    const int r = tid & 127;
    const int half = tid >> 7;
    const int jset = half * 8;
    const int rby = sY[r], rbx = sX[r], rbb = sBase[r];
    const float ascl = sScl[r];
    const float* Wrow = Wbase + (size_t)(bn + r) * p.K;

    const int w = tid >> 5, lane = tid & 31;
    const int wm = (w & 1) * 64, wn = (w >> 1) * 32;
    const int lg = lane >> 2, lk = lane & 3;

    const uint32_t sb = smem_u32(smem);
    const uint32_t aoff = (uint32_t)((lane & 15) * ROWB + (lane >> 4) * 16);
    const uint32_t boff = (uint32_t)(((lane & 7) + ((lane >> 4) << 3)) * ROWB
                                     + (lane & 8) * 2);

    float acc[4][4][4];
#pragma unroll
    for (int i = 0; i < 4; i++)
#pragma unroll
        for (int j = 0; j < 4; j++)
#pragma unroll
            for (int e = 0; e < 4; e++) acc[i][j][e] = 0.f;

    float avf[8], bvf[8];

    auto gather = [&](int k0) {
#pragma unroll
        for (int q = 0; q < 8; q++) {
            int k = k0 + jset + q;
            int ic = k / KHKW;
            int kk2 = k - ic * KHKW;
            int kh = kk2 / KW;
            int kw = kk2 - kh * KW;
            int ih = rby + kh, iw = rbx + kw;
            float v = 0.f;
            if ((unsigned)ih < (unsigned)IH && (unsigned)iw < (unsigned)IW) {
                int ii = (ic * IH + ih) * IW + iw;
                v = p.A[rbb + ii];
                if (RMS) v *= ascl * p.aweight[ii];
            }
            avf[q] = v;
        }
#pragma unroll
        for (int q4 = 0; q4 < 2; q4++) {
            float4 b = *(const float4*)(Wrow + k0 + jset + q4 * 4);
            bvf[q4 * 4 + 0] = b.x; bvf[q4 * 4 + 1] = b.y;
            bvf[q4 * 4 + 2] = b.z; bvf[q4 * 4 + 3] = b.w;
        }
    };
    auto store = [&](int buf) {
        char* base = smem + buf * BUFB;
        uint4 hv, lv;
        unsigned* hp = (unsigned*)&hv;
        unsigned* lp = (unsigned*)&lv;
        // A: h + l (both precisions)
#pragma unroll
        for (int c = 0; c < 4; c++) {
            float v0 = avf[2 * c], v1 = avf[2 * c + 1];
            if (PREC == 0) {
                unsigned ph = pack_bf16x2(v0, v1);
                hp[c] = ph;
                lp[c] = pack_bf16x2(v0 - __uint_as_float(ph << 16),
                                    v1 - __uint_as_float(ph & 0xFFFF0000u));
            } else {
                __half h0 = __float2half_rn(v0);
                __half h1 = __float2half_rn(v1);
                hp[c] = pack_f16x2(__half2float(h0), __half2float(h1));
                lp[c] = pack_f16x2(v0 - __half2float(h0), v1 - __half2float(h1));
            }
        }
        *(uint4*)(base + r * ROWB + half * 16) = hv;
        *(uint4*)(base + r * ROWB + 32 + half * 16) = lv;
        // B: h always; l only for bf16x3
        char* bb = base + TILEB;
#pragma unroll
        for (int c = 0; c < 4; c++) {
            float v0 = bvf[2 * c], v1 = bvf[2 * c + 1];
            if (PREC == 0) {
                unsigned ph = pack_bf16x2(v0, v1);
                hp[c] = ph;
                lp[c] = pack_bf16x2(v0 - __uint_as_float(ph << 16),
                                    v1 - __uint_as_float(ph & 0xFFFF0000u));
            } else {
                hp[c] = pack_f16x2(v0, v1);
            }
        }
        *(uint4*)(bb + r * ROWB + half * 16) = hv;
        if (PREC == 0) *(uint4*)(bb + r * ROWB + 32 + half * 16) = lv;
    };

    const int ntiles = p.K >> 4;
    gather(0);
    store(0);
    __syncthreads();

    for (int t = 0; t < ntiles; t++) {
        const int cur = t & 1;
        const uint32_t aBase = sb + cur * BUFB;
        const uint32_t bBase = aBase + TILEB;
        if (t + 1 < ntiles) gather((t + 1) << 4);

        unsigned bh[2][4], bl[2][4];
#pragma unroll
        for (int ntp = 0; ntp < 2; ntp++) {
            uint32_t ba = bBase + (uint32_t)((wn + ntp * 16) * ROWB) + boff;
            ldsm4(bh[ntp], ba);
            if (PREC == 0) ldsm4(bl[ntp], ba + 32);
        }
#pragma unroll
        for (int mt = 0; mt < 4; mt++) {
            uint32_t aa = aBase + (uint32_t)((wm + mt * 16) * ROWB) + aoff;
            unsigned ah[4], al[4];
            ldsm4(ah, aa);
            ldsm4(al, aa + 32);
#pragma unroll
            for (int nt = 0; nt < 4; nt++) {
                const unsigned* bhp = &bh[nt >> 1][(nt & 1) * 2];
                if (PREC == 0) {
                    const unsigned* blp = &bl[nt >> 1][(nt & 1) * 2];
                    mma_bf16(acc[mt][nt], ah, bhp);
                    mma_bf16(acc[mt][nt], al, bhp);
                    mma_bf16(acc[mt][nt], ah, blp);
                } else {
                    mma_f16(acc[mt][nt], ah, bhp);
                    mma_f16(acc[mt][nt], al, bhp);
                }
            }
        }
        if (t + 1 < ntiles) {
            store(cur ^ 1);
            __syncthreads();
        }
    }

    const int oHW = p.oHW;
    float sq0 = 0.f, sq1 = 0.f;
#pragma unroll
    for (int mt = 0; mt < 4; mt++) {
#pragma unroll
        for (int hf = 0; hf < 2; hf++) {
            int ml = wm + mt * 16 + lg + hf * 8;
            int obase = sObase[ml];
#pragma unroll
            for (int nt = 0; nt < 4; nt++) {
                int oc = bn + wn + nt * 8 + lk * 2;
                float v0 = acc[mt][nt][hf * 2 + 0];
                float v1 = acc[mt][nt][hf * 2 + 1];
                if (p.bias) { v0 += p.bias[oc]; v1 += p.bias[oc + 1]; }
                if (p.mode >= 1) { v0 = fmaxf(v0, 0.f); v1 = fmaxf(v1, 0.f); }
                size_t oi0 = (size_t)obase + (size_t)oc * oHW;
                size_t oi1 = oi0 + oHW;
                if (p.mode == 2) { v0 += p.res[oi0]; v1 += p.res[oi1]; }
                p.out[oi0] = v0;
                p.out[oi1] = v1;
                if (SQ) {
                    float s = v0 * v0 + v1 * v1;
                    if (ml < 64) sq0 += s; else sq1 += s;
                }
            }
        }
    }
    if (SQ) {
        rsum[0][tid] = sq0;
        rsum[1][tid] = sq1;
        __syncthreads();
        for (int st = 128; st > 0; st >>= 1) {
            if (tid < st) {
                rsum[0][tid] += rsum[0][tid + st];
                rsum[1][tid] += rsum[1][tid + st];
            }
            __syncthreads();
        }
        if (tid == 0) {
            p.sqout[(blockIdx.x * 2 + 0) * 2 + blockIdx.y] = rsum[0][0];
            p.sqout[(blockIdx.x * 2 + 1) * 2 + blockIdx.y] = rsum[1][0];
        }
    }
}

// ---------------------------------------------------------------------------
__global__ void enorm_kernel(const float* __restrict__ e, float* __restrict__ en) {
    int j = blockIdx.x * 256 + threadIdx.x;
    if (j >= NE) return;
    const float* r = e + (size_t)j * HS;
    float s = 0.f;
    for (int c = 0; c < HS; c++) { float v = r[c]; s += v * v; }
    en[j] = s;
}

__global__ __launch_bounds__(256) void vq_argmin_kernel(const float* __restrict__ scores,
                                                        const float* __restrict__ en,
                                                        const float* __restrict__ emb,
                                                        float* __restrict__ q,
                                                        float* __restrict__ tok_en) {
    int token = blockIdx.x * 8 + (threadIdx.x >> 5);
    int lane = threadIdx.x & 31;
    int n = token >> 6, hw = token & 63;
    const float* sc = scores + ((size_t)n * NE) * 64 + hw;
    float best = 3.4e38f;
    int bj = NE;
    for (int j = lane; j < NE; j += 32) {
        float d = en[j] - 2.f * sc[(size_t)j * 64];
        if (d < best || (d == best && j < bj)) { best = d; bj = j; }
    }
#pragma unroll
    for (int off = 16; off; off >>= 1) {
        float ob = __shfl_down_sync(0xffffffffu, best, off);
        int oj = __shfl_down_sync(0xffffffffu, bj, off);
        if (ob < best || (ob == best && oj < bj)) { best = ob; bj = oj; }
    }
    bj = __shfl_sync(0xffffffffu, bj, 0);
    const float* er = emb + (size_t)bj * HS;
    float* qp = q + (size_t)n * HS * 64 + hw;
    for (int c = lane; c < HS; c += 32) qp[(size_t)c * 64] = er[c];
    if (lane == 0) tok_en[token] = en[bj];
}

__global__ __launch_bounds__(256) void sqdiff_kernel(const float* __restrict__ a,
                                                     const float* __restrict__ b,
                                                     float* __restrict__ part, int nvec4) {
    const float4* a4 = (const float4*)a;
    const float4* b4 = (const float4*)b;
    float s = 0.f;
    for (int i = blockIdx.x * 256 + threadIdx.x; i < nvec4; i += 256 * 256) {
        float4 va = a4[i], vb = b4[i];
        float dx = va.x - vb.x, dy = va.y - vb.y, dz = va.z - vb.z, dw = va.w - vb.w;
        s += dx * dx + dy * dy + dz * dz + dw * dw;
    }
    __shared__ float sh[256];
    sh[threadIdx.x] = s;
    __syncthreads();
    for (int st = 128; st > 0; st >>= 1) {
        if (threadIdx.x < st) sh[threadIdx.x] += sh[threadIdx.x + st];
        __syncthreads();
    }
    if (threadIdx.x == 0) part[blockIdx.x] = sh[0];
}

__global__ void finalize_kernel(const float* __restrict__ partVq,
                                const float* __restrict__ partRec,
                                float* __restrict__ out) {
    if (threadIdx.x == 0 && blockIdx.x == 0) {
        float svq = 0.f, sre = 0.f;
        for (int i = 0; i < 256; i++) svq += partVq[i];
        for (int i = 0; i < 1024; i++) sre += partRec[i];
        float dict = svq * (1.f / 4194304.f);
        float rec = sre * (1.f / 786432.f);
        out[0] = rec + dict + dict;
        out[1] = rec;
        out[2] = dict;
        out[3] = dict;
    }
}

__global__ void prep_wp_kernel(const float* __restrict__ w, float* __restrict__ wp) {
    int idx = blockIdx.x * 256 + threadIdx.x;
    if (idx >= 1048576) return;
    int b = idx & 1;
    int a = (idx >> 1) & 1;
    int ic = (idx >> 2) & 255;
    int oc = (idx >> 10) & 255;
    int p = idx >> 18;
    int ph = p >> 1, pw = p & 1;
    int kh = ph + 2 * a, kw = pw + 2 * b;
    wp[idx] = w[((size_t)(ic * 256 + oc) * 4 + (3 - kh)) * 4 + (3 - kw)];
}

__global__ __launch_bounds__(256) void deconv2_kernel(const float* __restrict__ in,
                                                      const float* __restrict__ w,
                                                      const float* __restrict__ bias,
                                                      const float* __restrict__ x,
                                                      float* __restrict__ out,
                                                      float* __restrict__ partRec) {
    __shared__ float wsh[4 * 256 * 3];
    const int n = blockIdx.x;
    const int par = blockIdx.y;
    const int ph = par >> 1, pw = par & 1;
    const int tid = threadIdx.x;

    for (int idx = tid; idx < 3072; idx += 256) {
        int oc = idx % 3;
        int rest = idx / 3;
        int ic = rest & 255;
        int t = rest >> 8;
        int a = t >> 1, b = t & 1;
        int kh = ph + 2 * a, kw = pw + 2 * b;
        wsh[idx] = w[((size_t)(ic * 3 + oc) * 4 + (3 - kh)) * 4 + (3 - kw)];
    }
    __syncthreads();

    const int i = tid >> 4, j = tid & 15;
    const int oh = 2 * i + ph, ow = 2 * j + pw;
    float acc0 = 0.f, acc1 = 0.f, acc2 = 0.f;

    int base[4];
    bool ok[4];
#pragma unroll
    for (int t = 0; t < 4; t++) {
        int a = t >> 1, b = t & 1;
        int ih = i + ph + a - 1, iw = j + pw + b - 1;
        ok[t] = ((unsigned)ih < 16u) && ((unsigned)iw < 16u);
        base[t] = ok[t] ? (n * 65536 + ih * 16 + iw) : 0;
    }
    for (int ic = 0; ic < 256; ic++) {
        int ico = ic * 256;
#pragma unroll
        for (int t = 0; t < 4; t++) {
            if (ok[t]) {
                float v = in[base[t] + ico];
                const float* wp2 = &wsh[(t * 256 + ic) * 3];
                acc0 += v * wp2[0];
                acc1 += v * wp2[1];
                acc2 += v * wp2[2];
            }
        }
    }
    size_t o = (size_t)n * 3072 + (size_t)oh * 32 + ow;
    float v0 = acc0 + bias[0];
    float v1 = acc1 + bias[1];
    float v2 = acc2 + bias[2];
    out[o] = v0;
    out[o + 1024] = v1;
    out[o + 2048] = v2;
    float d0 = v0 - x[o], d1 = v1 - x[o + 1024], d2 = v2 - x[o + 2048];
    float ds = d0 * d0 + d1 * d1 + d2 * d2;
    __shared__ float rs[256];
    rs[tid] = ds;
    __syncthreads();
    for (int st = 128; st > 0; st >>= 1) {
        if (tid < st) rs[tid] += rs[tid + st];
        __syncthreads();
    }
    if (tid == 0) partRec[n * 4 + par] = rs[0];
}

// ---------------------------------------------------------------------------
static GemmP mkP(const float* A, const float* W, const float* bias, const float* res,
                 float* out, const float* sqin, const float* tokin, const float* aweight,
                 float* sqout,
                 int N, int K, int IC, int IH, int IW, int OH, int OW,
                 int stride, int padh, int padw,
                 int oscale, int ooffh, int ooffw, int oW, int oHW, int mode) {
    GemmP p;
    p.A = A; p.W = W; p.bias = bias; p.res = res; p.out = out;
    p.sqin = sqin; p.tokin = tokin; p.aweight = aweight; p.sqout = sqout;
    p.N = N; p.K = K; p.IC = IC; p.IH = IH; p.IW = IW; p.OH = OH; p.OW = OW;
    p.stride = stride; p.padh = padh; p.padw = padw;
    p.oscale = oscale; p.ooffh = ooffh; p.ooffw = ooffw; p.oW = oW; p.oHW = oHW;
    p.mode = mode;
    return p;
}

// PREC per res block
template<int PREC>
static void res_block(float* x, float* tmp,
                      const float* sqinX, const float* tokinX,
                      float* pT, float* pX2,
                      const float* rmsw,
                      const float* w3, const float* b3,
                      const float* w1, const float* b1) {
    {
        GemmP p = mkP(x, w3, b3, x, tmp, sqinX, tokinX, rmsw, pT,
                      256, 2304, 256, 8, 8, 8, 8, 1, 1, 1,
                      1, 0, 0, 8, 64, 2);
        conv_mma<3, 3, true, false, true, PREC><<<dim3(128, 2), 256>>>(p);
    }
    if (pX2) {
        GemmP p = mkP(tmp, w1, b1, tmp, x, pT, nullptr, rmsw + 16384, pX2,
                      256, 256, 256, 8, 8, 8, 8, 1, 0, 0,
                      1, 0, 0, 8, 64, 2);
        conv_mma<1, 1, true, false, true, PREC><<<dim3(128, 2), 256>>>(p);
    } else {
        GemmP p = mkP(tmp, w1, b1, tmp, x, pT, nullptr, rmsw + 16384, nullptr,
                      256, 256, 256, 8, 8, 8, 8, 1, 0, 0,
                      1, 0, 0, 8, 64, 2);
        conv_mma<1, 1, true, false, false, PREC><<<dim3(128, 2), 256>>>(p);
    }
}

extern "C" void kernel_launch(void* const* d_in, const int* in_sizes, int n_in,
                              void* d_out, int out_size) {
    const float* x       = (const float*)d_in[0];
    const float* enc_w1  = (const float*)d_in[1];
    const float* enc_b1  = (const float*)d_in[2];
    const float* enc_w2  = (const float*)d_in[3];
    const float* enc_b2  = (const float*)d_in[4];
    const float* rms_w   = (const float*)d_in[5];
    const float* c3_w    = (const float*)d_in[6];
    const float* c3_b    = (const float*)d_in[7];
    const float* c1_w    = (const float*)d_in[8];
    const float* c1_b    = (const float*)d_in[9];
    const float* emb     = (const float*)d_in[10];
    const float* dec_w1  = (const float*)d_in[11];
    const float* dec_b1  = (const float*)d_in[12];
    const float* dec_w2  = (const float*)d_in[13];
    const float* dec_b2  = (const float*)d_in[14];
    float* out = (float*)d_out;

    float *h16, *h8, *t8, *q, *scores, *wp, *en, *tok, *pA, *pB, *part;
    cudaGetSymbolAddress((void**)&h16, g_h16);
    cudaGetSymbolAddress((void**)&h8, g_h8);
    cudaGetSymbolAddress((void**)&t8, g_t8);
    cudaGetSymbolAddress((void**)&q, g_q);
    cudaGetSymbolAddress((void**)&scores, g_scores);
    cudaGetSymbolAddress((void**)&wp, g_wp);
    cudaGetSymbolAddress((void**)&en, g_enorm);
    cudaGetSymbolAddress((void**)&tok, g_tok_en);
    cudaGetSymbolAddress((void**)&pA, g_pA);
    cudaGetSymbolAddress((void**)&pB, g_pB);
    cudaGetSymbolAddress((void**)&part, g_part);

    // ---- Encoder (bf16x3) ----
    {
        GemmP p = mkP(x, enc_w1, enc_b1, nullptr, h16, nullptr, nullptr, nullptr, nullptr,
                      256, 48, 3, 32, 32, 16, 16, 2, 1, 1,
                      1, 0, 0, 16, 256, 1);
        conv_mma<4, 4, false, false, false, 0><<<dim3(512, 2), 256>>>(p);
    }
    {
        GemmP p = mkP(h16, enc_w2, enc_b2, nullptr, h8, nullptr, nullptr, nullptr, pA,
                      256, 4096, 256, 16, 16, 8, 8, 2, 1, 1,
                      1, 0, 0, 8, 64, 1);
        conv_mma<4, 4, false, false, true, 0><<<dim3(128, 2), 256>>>(p);
    }
    res_block<0>(h8, t8, pA, nullptr, pB, pA, rms_w + 0 * 32768,
                 c3_w + 0 * 589824, c3_b + 0 * 256, c1_w + 0 * 65536, c1_b + 0 * 256);
    res_block<0>(h8, t8, pA, nullptr, pB, nullptr, rms_w + 1 * 32768,
                 c3_w + 1 * 589824, c3_b + 1 * 256, c1_w + 1 * 65536, c1_b + 1 * 256);

    // ---- VQ (bf16x3 scores; argmin + gather exact) ----
    enorm_kernel<<<2, 256>>>(emb, en);
    {
        GemmP p = mkP(h8, emb, nullptr, nullptr, scores, nullptr, nullptr, nullptr, nullptr,
                      512, 256, 256, 8, 8, 8, 8, 1, 0, 0,
                      1, 0, 0, 8, 64, 0);
        conv_mma<1, 1, false, false, false, 0><<<dim3(128, 4), 256>>>(p);
    }
    vq_argmin_kernel<<<2048, 256>>>(scores, en, emb, q, tok);
    sqdiff_kernel<<<256, 256>>>(h8, q, part, 1048576);

    // ---- Decoder (fp16x2: post-argmin, 2 MMA/k16) ----
    res_block<1>(q, t8, nullptr, tok, pB, pA, rms_w + 2 * 32768,
                 c3_w + 2 * 589824, c3_b + 2 * 256, c1_w + 2 * 65536, c1_b + 2 * 256);
    res_block<1>(q, t8, pA, nullptr, pB, nullptr, rms_w + 3 * 32768,
                 c3_w + 3 * 589824, c3_b + 3 * 256, c1_w + 3 * 65536, c1_b + 3 * 256);

    prep_wp_kernel<<<4096, 256>>>(dec_w1, wp);
    {
        GemmP p = mkP(q, wp, dec_b1, nullptr, h16, nullptr, nullptr, nullptr, nullptr,
                      256, 1024, 256, 8, 8, 8, 8, 1, 0, 0,
                      2, 0, 0, 16, 256, 1);
        conv_mma<2, 2, false, true, false, 1><<<dim3(128, 2, 4), 256>>>(p);
    }

    deconv2_kernel<<<dim3(256, 4), 256>>>(h16, dec_w2, dec_b2, x, out + 4, part + 256);

    finalize_kernel<<<1, 32>>>(part, part + 256, out);
}